// round 1
// baseline (speedup 1.0000x reference)
#include <cuda_runtime.h>
#include <math.h>

#define NS   16
#define LL   256
#define HH   128
#define LAMF 20.0f
#define EPSF 1e-8f
#define NARC (NS * LL * LL)   // 1,048,576

// -------- scratch (allocation-free: device globals) --------
__device__ __align__(16) float g_K [NARC];   // holds C, then K = exp(-LAM*Cn)
__device__ __align__(16) float g_KM[NARC];   // K * Cn
__device__ __align__(16) float g_rT[NARC];   // softmax(scores) transposed: [n][i][row]
__device__ __align__(16) float g_cT[NARC];   // normalized head transposed: [n][j][row]
__device__ __align__(16) float g_U [NARC];   // u  [n][i][row]
__device__ __align__(16) float g_B [NARC];   // b/v [n][j][row]
__device__ unsigned int g_maxabs[NS];

// -------- init: U = 1/256, zero max-abs + loss --------
__global__ void init_kernel(float* __restrict__ loss) {
    int idx = blockIdx.x * blockDim.x + threadIdx.x;
    g_U[idx] = 1.0f / 256.0f;
    if (idx < NS) g_maxabs[idx] = 0u;
    if (idx == 0) *loss = 0.0f;
}

// -------- MLP: scores = tanh(F@W1 + b1) @ W2 + b2,  F = (NARC, 128) --------
// block: 256 threads, BM=64 rows, full N=128 in registers (TM=8, TN=4)
__global__ void __launch_bounds__(256) mlp_kernel(
    const float* __restrict__ f,  const float* __restrict__ W1,
    const float* __restrict__ b1, const float* __restrict__ W2,
    const float* __restrict__ b2, float* __restrict__ scores)
{
    __shared__ float As[8][65];     // [k][m], padded
    __shared__ float Bs[8][128];    // [k][n]
    int tid = threadIdx.x;
    int tx = tid & 31, ty = tid >> 5;           // ty = warp id (0..7)
    size_t row0 = (size_t)blockIdx.x * 64;
    const float* fb = f + row0 * HH;

    float acc[8][4];
#pragma unroll
    for (int i = 0; i < 8; i++)
#pragma unroll
        for (int j = 0; j < 4; j++) acc[i][j] = 0.0f;

    int am = tid >> 2, ak = (tid & 3) * 2;      // A: 64 rows x 8 k, float2/thread
    int bk = tid >> 5, bc = (tid & 31) * 4;     // B: 8 k x 128 n, float4/thread

    for (int kk = 0; kk < HH; kk += 8) {
        float2 a2 = *(const float2*)(fb + (size_t)am * HH + kk + ak);
        As[ak][am] = a2.x; As[ak + 1][am] = a2.y;
        *(float4*)&Bs[bk][bc] = *(const float4*)(W1 + (size_t)(kk + bk) * HH + bc);
        __syncthreads();
#pragma unroll
        for (int k = 0; k < 8; k++) {
            float4 b = *(float4*)&Bs[k][tx * 4];
#pragma unroll
            for (int i = 0; i < 8; i++) {
                float a = As[k][ty + 8 * i];
                acc[i][0] += a * b.x; acc[i][1] += a * b.y;
                acc[i][2] += a * b.z; acc[i][3] += a * b.w;
            }
        }
        __syncthreads();
    }

    float4 b1v = *(const float4*)(b1 + tx * 4);
    float4 w2v = *(const float4*)(W2 + tx * 4);
    float bias2 = b2[0];
#pragma unroll
    for (int i = 0; i < 8; i++) {
        float s = tanhf(acc[i][0] + b1v.x) * w2v.x
                + tanhf(acc[i][1] + b1v.y) * w2v.y
                + tanhf(acc[i][2] + b1v.z) * w2v.z
                + tanhf(acc[i][3] + b1v.w) * w2v.w;
#pragma unroll
        for (int o = 16; o > 0; o >>= 1) s += __shfl_xor_sync(0xffffffffu, s, o);
        if (tx == 0) scores[row0 + ty + 8 * i] = s + bias2;
    }
}

// -------- cost: C[n,i,j] = dot(f[n,i,j,:], f[n,j,i,:]); symmetric, j>=i only --------
__global__ void cost_kernel(const float* __restrict__ f) {
    int n = blockIdx.y;
    int gw = blockIdx.x * 8 + (threadIdx.x >> 5);   // 512 warps / sample
    int lane = threadIdx.x & 31;
    const float* fn = f + (size_t)n * LL * LL * HH;
    float* C = g_K + (size_t)n * LL * LL;
    float lmax = 0.0f;
    for (int a = gw; a < LL * LL; a += 512) {
        int i = a >> 8, j = a & 255;
        if (j < i) continue;
        float4 x = *((const float4*)(fn + (size_t)(i * LL + j) * HH) + lane);
        float4 y = *((const float4*)(fn + (size_t)(j * LL + i) * HH) + lane);
        float s = x.x * y.x + x.y * y.y + x.z * y.z + x.w * y.w;
#pragma unroll
        for (int o = 16; o > 0; o >>= 1) s += __shfl_xor_sync(0xffffffffu, s, o);
        if (lane == 0) {
            C[i * LL + j] = s;
            C[j * LL + i] = s;
            lmax = fmaxf(lmax, fabsf(s));
        }
    }
    if (lane == 0) atomicMax(&g_maxabs[n], __float_as_uint(lmax));
}

// -------- K = exp(-LAM*Cn), KM = K*Cn (in place over C) --------
__global__ void kexp_kernel() {
    int idx = blockIdx.x * blockDim.x + threadIdx.x;
    int n = idx >> 16;
    float mx = __uint_as_float(g_maxabs[n]);
    float cn = g_K[idx] / (mx + EPSF);
    float k = expf(-LAMF * cn);
    g_K[idx]  = k;
    g_KM[idx] = k * cn;
}

// -------- rT: softmax over score rows, stored transposed [n][i][row] --------
__global__ void softmaxT_kernel(const float* __restrict__ scores) {
    __shared__ float sh[32][257];
    int blk = blockIdx.x;
    int n  = blk >> 3;
    int r0 = (blk & 7) << 5;
    int tid = threadIdx.x;
    int wid = tid >> 5, lane = tid & 31;
    const float* S = scores + ((size_t)n * 256 + r0) * 256;
#pragma unroll
    for (int s4 = 0; s4 < 4; s4++) {
        int rl = wid + 8 * s4;
        const float* row = S + rl * 256;
        float4 v0 = *(const float4*)(row + lane * 4);
        float4 v1 = *(const float4*)(row + 128 + lane * 4);
        float m = fmaxf(fmaxf(fmaxf(v0.x, v0.y), fmaxf(v0.z, v0.w)),
                        fmaxf(fmaxf(v1.x, v1.y), fmaxf(v1.z, v1.w)));
#pragma unroll
        for (int o = 16; o > 0; o >>= 1) m = fmaxf(m, __shfl_xor_sync(0xffffffffu, m, o));
        float e[8];
        e[0] = expf(v0.x - m); e[1] = expf(v0.y - m);
        e[2] = expf(v0.z - m); e[3] = expf(v0.w - m);
        e[4] = expf(v1.x - m); e[5] = expf(v1.y - m);
        e[6] = expf(v1.z - m); e[7] = expf(v1.w - m);
        float sum = e[0]+e[1]+e[2]+e[3]+e[4]+e[5]+e[6]+e[7];
#pragma unroll
        for (int o = 16; o > 0; o >>= 1) sum += __shfl_xor_sync(0xffffffffu, sum, o);
        float inv = 1.0f / sum;
#pragma unroll
        for (int q = 0; q < 4; q++) sh[rl][lane * 4 + q]       = e[q] * inv;
#pragma unroll
        for (int q = 0; q < 4; q++) sh[rl][128 + lane * 4 + q] = e[4 + q] * inv;
    }
    __syncthreads();
    int rloc = tid & 31, cb = tid >> 5;
    float* O = g_rT + (size_t)n * 65536 + r0;
#pragma unroll
    for (int s = 0; s < 32; s++) {
        int col = cb + 8 * s;
        O[(size_t)col * 256 + rloc] = sh[rloc][col];
    }
}

// -------- cT: (head+eps)/rowsum, stored transposed [n][j][row] --------
__global__ void normT_kernel(const float* __restrict__ head) {
    __shared__ float sh[32][257];
    int blk = blockIdx.x;
    int n  = blk >> 3;
    int r0 = (blk & 7) << 5;
    int tid = threadIdx.x;
    int wid = tid >> 5, lane = tid & 31;
    const float* S = head + ((size_t)n * 256 + r0) * 256;
#pragma unroll
    for (int s4 = 0; s4 < 4; s4++) {
        int rl = wid + 8 * s4;
        const float* row = S + rl * 256;
        float4 v0 = *(const float4*)(row + lane * 4);
        float4 v1 = *(const float4*)(row + 128 + lane * 4);
        float e[8] = { v0.x + EPSF, v0.y + EPSF, v0.z + EPSF, v0.w + EPSF,
                       v1.x + EPSF, v1.y + EPSF, v1.z + EPSF, v1.w + EPSF };
        float sum = e[0]+e[1]+e[2]+e[3]+e[4]+e[5]+e[6]+e[7];
#pragma unroll
        for (int o = 16; o > 0; o >>= 1) sum += __shfl_xor_sync(0xffffffffu, sum, o);
        float inv = 1.0f / sum;
#pragma unroll
        for (int q = 0; q < 4; q++) sh[rl][lane * 4 + q]       = e[q] * inv;
#pragma unroll
        for (int q = 0; q < 4; q++) sh[rl][128 + lane * 4 + q] = e[4 + q] * inv;
    }
    __syncthreads();
    int rloc = tid & 31, cb = tid >> 5;
    float* O = g_cT + (size_t)n * 65536 + r0;
#pragma unroll
    for (int s = 0; s < 32; s++) {
        int col = cb + 8 * s;
        O[(size_t)col * 256 + rloc] = sh[rloc][col];
    }
}

// -------- Sinkhorn step: Out = Numer / (K @ X + eps), batched over n --------
// phase 0: B = cT / (K@U + eps)     phase 1: U = rT / (K@B + eps)
// (K is symmetric, so K^T @ x == K @ x)
__global__ void __launch_bounds__(256) gemm_div_kernel(int phase) {
    __shared__ float As[16][65];
    __shared__ float Bs[16][64];
    const float* X  = phase ? g_B  : g_U;
    const float* Nm = phase ? g_rT : g_cT;
    float* O        = phase ? g_U  : g_B;
    int n = blockIdx.z;
    const float* A  = g_K + (size_t)n * 65536;
    const float* Xn = X   + (size_t)n * 65536;
    int i0 = blockIdx.y * 64, c0 = blockIdx.x * 64;
    int tid = threadIdx.x;
    int tx = tid & 15, ty = tid >> 4;
    float acc[4][4];
#pragma unroll
    for (int i = 0; i < 4; i++)
#pragma unroll
        for (int j = 0; j < 4; j++) acc[i][j] = 0.0f;

    int am = tid >> 2, akq = (tid & 3) * 4;
    int bk = tid >> 4, bcq = (tid & 15) * 4;

    for (int kk = 0; kk < 256; kk += 16) {
        float4 av = *(const float4*)(A + (size_t)(i0 + am) * 256 + kk + akq);
        As[akq][am] = av.x; As[akq+1][am] = av.y; As[akq+2][am] = av.z; As[akq+3][am] = av.w;
        *(float4*)&Bs[bk][bcq] = *(const float4*)(Xn + (size_t)(kk + bk) * 256 + c0 + bcq);
        __syncthreads();
#pragma unroll
        for (int k = 0; k < 16; k++) {
            float4 b = *(float4*)&Bs[k][tx * 4];
            float a0 = As[k][ty], a1 = As[k][ty+16], a2 = As[k][ty+32], a3 = As[k][ty+48];
            acc[0][0]+=a0*b.x; acc[0][1]+=a0*b.y; acc[0][2]+=a0*b.z; acc[0][3]+=a0*b.w;
            acc[1][0]+=a1*b.x; acc[1][1]+=a1*b.y; acc[1][2]+=a1*b.z; acc[1][3]+=a1*b.w;
            acc[2][0]+=a2*b.x; acc[2][1]+=a2*b.y; acc[2][2]+=a2*b.z; acc[2][3]+=a2*b.w;
            acc[3][0]+=a3*b.x; acc[3][1]+=a3*b.y; acc[3][2]+=a3*b.z; acc[3][3]+=a3*b.w;
        }
        __syncthreads();
    }
#pragma unroll
    for (int i = 0; i < 4; i++) {
        size_t off = (size_t)n * 65536 + (size_t)(i0 + ty + 16 * i) * 256 + c0 + tx * 4;
        float4 nm = *(const float4*)(Nm + off);
        float4 o;
        o.x = nm.x / (acc[i][0] + EPSF);
        o.y = nm.y / (acc[i][1] + EPSF);
        o.z = nm.z / (acc[i][2] + EPSF);
        o.w = nm.w / (acc[i][3] + EPSF);
        *(float4*)(O + off) = o;
    }
}

// -------- final: loss += sum( U .* (KM @ V) ),  V lives in g_B --------
__global__ void __launch_bounds__(256) gemm_dot_kernel(float* __restrict__ loss) {
    __shared__ float As[16][65];
    __shared__ float Bs[16][64];
    __shared__ float red[8];
    int n = blockIdx.z;
    const float* A  = g_KM + (size_t)n * 65536;
    const float* Xn = g_B  + (size_t)n * 65536;
    int i0 = blockIdx.y * 64, c0 = blockIdx.x * 64;
    int tid = threadIdx.x;
    int tx = tid & 15, ty = tid >> 4;
    float acc[4][4];
#pragma unroll
    for (int i = 0; i < 4; i++)
#pragma unroll
        for (int j = 0; j < 4; j++) acc[i][j] = 0.0f;

    int am = tid >> 2, akq = (tid & 3) * 4;
    int bk = tid >> 4, bcq = (tid & 15) * 4;

    for (int kk = 0; kk < 256; kk += 16) {
        float4 av = *(const float4*)(A + (size_t)(i0 + am) * 256 + kk + akq);
        As[akq][am] = av.x; As[akq+1][am] = av.y; As[akq+2][am] = av.z; As[akq+3][am] = av.w;
        *(float4*)&Bs[bk][bcq] = *(const float4*)(Xn + (size_t)(kk + bk) * 256 + c0 + bcq);
        __syncthreads();
#pragma unroll
        for (int k = 0; k < 16; k++) {
            float4 b = *(float4*)&Bs[k][tx * 4];
            float a0 = As[k][ty], a1 = As[k][ty+16], a2 = As[k][ty+32], a3 = As[k][ty+48];
            acc[0][0]+=a0*b.x; acc[0][1]+=a0*b.y; acc[0][2]+=a0*b.z; acc[0][3]+=a0*b.w;
            acc[1][0]+=a1*b.x; acc[1][1]+=a1*b.y; acc[1][2]+=a1*b.z; acc[1][3]+=a1*b.w;
            acc[2][0]+=a2*b.x; acc[2][1]+=a2*b.y; acc[2][2]+=a2*b.z; acc[2][3]+=a2*b.w;
            acc[3][0]+=a3*b.x; acc[3][1]+=a3*b.y; acc[3][2]+=a3*b.z; acc[3][3]+=a3*b.w;
        }
        __syncthreads();
    }
    float s = 0.0f;
#pragma unroll
    for (int i = 0; i < 4; i++) {
        size_t off = (size_t)n * 65536 + (size_t)(i0 + ty + 16 * i) * 256 + c0 + tx * 4;
        float4 u = *(const float4*)(g_U + off);
        s += u.x * acc[i][0] + u.y * acc[i][1] + u.z * acc[i][2] + u.w * acc[i][3];
    }
    int wid = tid >> 5, lane = tid & 31;
#pragma unroll
    for (int o = 16; o > 0; o >>= 1) s += __shfl_xor_sync(0xffffffffu, s, o);
    if (lane == 0) red[wid] = s;
    __syncthreads();
    if (tid == 0) {
        float t = 0.0f;
#pragma unroll
        for (int w = 0; w < 8; w++) t += red[w];
        atomicAdd(loss, t);
    }
}

extern "C" void kernel_launch(void* const* d_in, const int* in_sizes, int n_in,
                              void* d_out, int out_size)
{
    const float* f    = (const float*)d_in[0];
    const float* head = (const float*)d_in[1];
    const float* W1   = (const float*)d_in[2];
    const float* b1   = (const float*)d_in[3];
    const float* W2   = (const float*)d_in[4];
    const float* b2   = (const float*)d_in[5];
    float* out    = (float*)d_out;
    float* scores = out;
    float* loss   = out + (out_size - 1);

    init_kernel<<<NARC / 256, 256>>>(loss);
    mlp_kernel<<<NARC / 64, 256>>>(f, W1, b1, W2, b2, scores);
    cost_kernel<<<dim3(64, NS), 256>>>(f);
    kexp_kernel<<<NARC / 256, 256>>>();
    softmaxT_kernel<<<128, 256>>>(scores);
    normT_kernel<<<128, 256>>>(head);
    for (int it = 0; it < 20; ++it) {
        gemm_div_kernel<<<dim3(4, 4, NS), 256>>>(0);   // B = cT/(K@U+eps)
        gemm_div_kernel<<<dim3(4, 4, NS), 256>>>(1);   // U = rT/(K@B+eps)
    }
    gemm_div_kernel<<<dim3(4, 4, NS), 256>>>(0);       // V = cT/(K@U+eps) -> g_B
    gemm_dot_kernel<<<dim3(4, 4, NS), 256>>>(loss);    // loss = sum(U .* (KM@V))
}

// round 3
// speedup vs baseline: 1.3650x; 1.3650x over previous
#include <cuda_runtime.h>
#include <cuda_bf16.h>
#include <math.h>
#include <stdint.h>

#define NS   16
#define LL   256
#define HH   128
#define LAMF 20.0f
#define EPSF 1e-8f
#define NARC (NS * LL * LL)   // 1,048,576
#define NCHUNK 8192           // 128 rows per chunk
#define MLP_GRID 148

// -------- scratch (allocation-free: device globals) --------
__device__ __align__(16) float g_K [NARC];
__device__ __align__(16) float g_KM[NARC];
__device__ __align__(16) float g_rT[NARC];
__device__ __align__(16) float g_cT[NARC];
__device__ __align__(16) float g_U [NARC];
__device__ __align__(16) float g_B [NARC];
__device__ unsigned int g_maxabs[NS];
__device__ __align__(16) unsigned int g_Whi[8704];   // W1 bf16-hi, padded [k][n] pitch 136
__device__ __align__(16) unsigned int g_Wlo[8704];   // W1 bf16-lo

// ================= PTX helpers (baseline sm_103 — no 'a' features!) =================
__device__ __forceinline__ uint32_t smem_u32(const void* p) {
    uint32_t a;
    asm("{ .reg .u64 t; cvta.to.shared.u64 t, %1; cvt.u32.u64 %0, t; }" : "=r"(a) : "l"(p));
    return a;
}
#define MBAR_INIT(addr, cnt) \
    asm volatile("mbarrier.init.shared.b64 [%0], %1;" :: "r"(addr), "r"(cnt) : "memory")
#define MBAR_ARRIVE(addr) \
    asm volatile("mbarrier.arrive.shared.b64 _, [%0];" :: "r"(addr) : "memory")
#define MBAR_WAIT(addr, ph) do { \
    uint32_t _m = (addr); uint32_t _p = (ph); uint32_t _d; \
    asm volatile("{\n\t.reg .pred p;\n\tmbarrier.try_wait.parity.acquire.cta.shared::cta.b64 p, [%1], %2;\n\tselp.b32 %0, 1, 0, p;\n\t}" \
        : "=r"(_d) : "r"(_m), "r"(_p) : "memory"); \
    if (!_d) { \
        asm volatile("{\n\t.reg .pred P1;\n\tWL_%=:\n\tmbarrier.try_wait.parity.acquire.cta.shared::cta.b64 P1, [%0], %1, 0x989680;\n\t@P1 bra.uni WD_%=;\n\tbra.uni WL_%=;\n\tWD_%=:\n\t}" \
            :: "r"(_m), "r"(_p) : "memory"); \
    } } while (0)

#define LDSM_X4(r, addr) \
    asm volatile("ldmatrix.sync.aligned.m8n8.x4.shared.b16 {%0,%1,%2,%3}, [%4];" \
        : "=r"((r)[0]), "=r"((r)[1]), "=r"((r)[2]), "=r"((r)[3]) : "r"(addr))
#define LDSM_X4T(r, addr) \
    asm volatile("ldmatrix.sync.aligned.m8n8.x4.trans.shared.b16 {%0,%1,%2,%3}, [%4];" \
        : "=r"((r)[0]), "=r"((r)[1]), "=r"((r)[2]), "=r"((r)[3]) : "r"(addr))
#define MMA_BF16(d, a, b) \
    asm volatile("mma.sync.aligned.m16n8k16.row.col.f32.bf16.bf16.f32 " \
        "{%0,%1,%2,%3}, {%4,%5,%6,%7}, {%8,%9}, {%0,%1,%2,%3};" \
        : "+f"((d)[0]), "+f"((d)[1]), "+f"((d)[2]), "+f"((d)[3]) \
        : "r"((a)[0]), "r"((a)[1]), "r"((a)[2]), "r"((a)[3]), "r"((b)[0]), "r"((b)[1]))

__device__ __forceinline__ uint32_t pack_bf16(__nv_bfloat16 a, __nv_bfloat16 b) {
    __nv_bfloat162 p = __halves2bfloat162(a, b);
    return *reinterpret_cast<uint32_t*>(&p);
}
__device__ __forceinline__ float ftanh(float x) {
    float e = __expf(2.0f * x);
    return 1.0f - __fdividef(2.0f, e + 1.0f);
}

// -------- init: U = 1/256, zero max-abs + loss --------
__global__ void init_kernel(float* __restrict__ loss) {
    int idx = blockIdx.x * blockDim.x + threadIdx.x;
    g_U[idx] = 1.0f / 256.0f;
    if (idx < NS) g_maxabs[idx] = 0u;
    if (idx == 0) *loss = 0.0f;
}

// -------- prep: W1 -> split bf16 hi/lo, padded row-major [k][n], pitch 136 bf16 --------
__global__ void prep_w_kernel(const float* __restrict__ W1) {
    int idx = blockIdx.x * 256 + threadIdx.x;   // 16384 elems
    int k = idx >> 7, n = idx & 127;
    float x = W1[idx];
    __nv_bfloat16 h = __float2bfloat16(x);
    float l = x - __bfloat162float(h);
    int off = k * 136 + n;
    ((__nv_bfloat16*)g_Whi)[off] = h;
    ((__nv_bfloat16*)g_Wlo)[off] = __float2bfloat16(l);
}

// ============ MLP via mma.sync bf16 (split hi/lo), warp-specialized persistent ============
// smem bytes:
//   16..47: mbarriers full[2]@16/24, free[2]@32/40
//   64: sp[2][128] floats (1024B) | 1088: b1[128] | 1600: w2[128]
//   2176: Whi (34816) | 36992: Wlo (34816)
//   71808 + s*69632: Ahi (34816), Alo (34816)
#define PITCHB  272
#define ATILE   34816
#define B1S_OFF 1088
#define W2S_OFF 1600
#define WHI_OFF 2176
#define WLO_OFF 36992
#define A_OFF   71808
#define SP_OFF  64
#define MLP_SMEM 211072

__global__ void __launch_bounds__(384, 1) mlp_mma_kernel(
    const float* __restrict__ f,  const float* __restrict__ b1,
    const float* __restrict__ W2, const float* __restrict__ b2,
    float* __restrict__ scores)
{
    extern __shared__ __align__(1024) char smem[];
    const uint32_t sb = smem_u32(smem);
    const int tid = threadIdx.x;

    if (tid == 0) {
        MBAR_INIT(sb + 16, 128); MBAR_INIT(sb + 24, 128);   // full[s]: producers
        MBAR_INIT(sb + 32, 256); MBAR_INIT(sb + 40, 256);   // free[s]: consumers
    }
    // stage W tiles + b1 + w2 into smem
    for (int i = tid; i < 8704; i += 384) {
        ((uint32_t*)(smem + WHI_OFF))[i] = g_Whi[i];
        ((uint32_t*)(smem + WLO_OFF))[i] = g_Wlo[i];
    }
    if (tid < 128) {
        ((float*)(smem + B1S_OFF))[tid] = b1[tid];
        ((float*)(smem + W2S_OFF))[tid] = W2[tid];
    }
    __syncthreads();

    if (tid >= 256) {
        // ================= PRODUCERS (warps 8-11, 128 threads) =================
        const int ptid = tid - 256;
        int lc = 0;
        for (int chunk = blockIdx.x; chunk < NCHUNK; chunk += MLP_GRID, ++lc) {
            const int s = lc & 1;
            if (lc >= 2) MBAR_WAIT(sb + 32 + s * 8, ((lc >> 1) - 1) & 1);
            const float4* src = (const float4*)(f + (size_t)chunk * 16384);
            char* ahi = smem + A_OFF + s * (2 * ATILE);
            char* alo = ahi + ATILE;
#pragma unroll 4
            for (int q = 0; q < 32; q++) {
                int idx = q * 128 + ptid;
                float4 v = __ldg(src + idx);
                int row = idx >> 5, colq = (idx & 31) << 2;
                int off = row * PITCHB + colq * 2;
                __nv_bfloat16 h0 = __float2bfloat16(v.x);
                __nv_bfloat16 h1 = __float2bfloat16(v.y);
                __nv_bfloat16 h2 = __float2bfloat16(v.z);
                __nv_bfloat16 h3 = __float2bfloat16(v.w);
                *(uint2*)(ahi + off) = make_uint2(pack_bf16(h0, h1), pack_bf16(h2, h3));
                *(uint2*)(alo + off) = make_uint2(
                    pack_bf16(__float2bfloat16(v.x - __bfloat162float(h0)),
                              __float2bfloat16(v.y - __bfloat162float(h1))),
                    pack_bf16(__float2bfloat16(v.z - __bfloat162float(h2)),
                              __float2bfloat16(v.w - __bfloat162float(h3))));
            }
            MBAR_ARRIVE(sb + 16 + s * 8);   // full[s] (release)
        }
    } else {
        // ================= CONSUMERS (warps 0-7, 256 threads) =================
        const int lane = tid & 31, wid = tid >> 5;
        const int warpM = wid >> 1, warpN = wid & 1;
        const int t = lane & 3, g = lane >> 2;
        const int lr = lane & 15, lh = lane >> 4;
        const float b2v = __ldg(b2);
        const float* sh_b1 = (const float*)(smem + B1S_OFF);
        const float* sh_w2 = (const float*)(smem + W2S_OFF);
        float* sp = (float*)(smem + SP_OFF);
        // ldmatrix base offsets (lane-dependent)
        const uint32_t a_off = (uint32_t)((warpM * 32 + lr) * PITCHB + lh * 16);
        const uint32_t b_off = (uint32_t)(lr * PITCHB + (warpN * 64 + lh * 8) * 2);

        int lc = 0;
        for (int chunk = blockIdx.x; chunk < NCHUNK; chunk += MLP_GRID, ++lc) {
            const int s = lc & 1;
            MBAR_WAIT(sb + 16 + s * 8, (lc >> 1) & 1);     // A[s] ready
            const uint32_t sa_hi = sb + A_OFF + s * (2 * ATILE);
            const uint32_t sa_lo = sa_hi + ATILE;

            float D[2][8][4];
#pragma unroll
            for (int i = 0; i < 2; i++)
#pragma unroll
                for (int j = 0; j < 8; j++)
#pragma unroll
                    for (int q = 0; q < 4; q++) D[i][j][q] = 0.0f;

#pragma unroll
            for (int ks = 0; ks < 8; ks++) {
                uint32_t ah0[4], ah1[4], al0[4], al1[4];
                LDSM_X4(ah0, sa_hi + a_off + ks * 32);
                LDSM_X4(ah1, sa_hi + a_off + 16 * PITCHB + ks * 32);
                LDSM_X4(al0, sa_lo + a_off + ks * 32);
                LDSM_X4(al1, sa_lo + a_off + 16 * PITCHB + ks * 32);
                uint32_t bh[8][2], bl[8][2];
#pragma unroll
                for (int p = 0; p < 4; p++) {
                    uint32_t r[4];
                    LDSM_X4T(r, sb + WHI_OFF + b_off + ks * (16 * PITCHB) + p * 32);
                    bh[2*p][0] = r[0]; bh[2*p][1] = r[1];
                    bh[2*p+1][0] = r[2]; bh[2*p+1][1] = r[3];
                    LDSM_X4T(r, sb + WLO_OFF + b_off + ks * (16 * PITCHB) + p * 32);
                    bl[2*p][0] = r[0]; bl[2*p][1] = r[1];
                    bl[2*p+1][0] = r[2]; bl[2*p+1][1] = r[3];
                }
#pragma unroll
                for (int nf = 0; nf < 8; nf++) {
                    MMA_BF16(D[0][nf], ah0, bh[nf]);
                    MMA_BF16(D[1][nf], ah1, bh[nf]);
                    MMA_BF16(D[0][nf], al0, bh[nf]);
                    MMA_BF16(D[1][nf], al1, bh[nf]);
                    MMA_BF16(D[0][nf], ah0, bl[nf]);
                    MMA_BF16(D[1][nf], ah1, bl[nf]);
                }
            }
            MBAR_ARRIVE(sb + 32 + s * 8);   // free[s] — producers may refill

            // ---- epilogue: score[row] = sum_n tanh(D+b1[n]) * w2[n] + b2 ----
            float out_lo[2], out_hi[2];
#pragma unroll
            for (int mf = 0; mf < 2; mf++) {
                float plo = 0.0f, phi = 0.0f;
#pragma unroll
                for (int nf = 0; nf < 8; nf++) {
                    int col = warpN * 64 + nf * 8 + 2 * t;
                    float b1a = sh_b1[col], b1b = sh_b1[col + 1];
                    float w2a = sh_w2[col], w2b = sh_w2[col + 1];
                    plo += ftanh(D[mf][nf][0] + b1a) * w2a + ftanh(D[mf][nf][1] + b1b) * w2b;
                    phi += ftanh(D[mf][nf][2] + b1a) * w2a + ftanh(D[mf][nf][3] + b1b) * w2b;
                }
                plo += __shfl_xor_sync(0xffffffffu, plo, 1);
                plo += __shfl_xor_sync(0xffffffffu, plo, 2);
                phi += __shfl_xor_sync(0xffffffffu, phi, 1);
                phi += __shfl_xor_sync(0xffffffffu, phi, 2);
                out_lo[mf] = plo; out_hi[mf] = phi;
            }
            const int par = lc & 1;
            if (warpN == 0 && t == 0) {
#pragma unroll
                for (int mf = 0; mf < 2; mf++) {
                    int row = warpM * 32 + mf * 16 + g;
                    sp[par * 128 + row]     = out_lo[mf];
                    sp[par * 128 + row + 8] = out_hi[mf];
                }
            }
            asm volatile("bar.sync 1, 256;" ::: "memory");
            if (warpN == 1 && t == 0) {
                float* so = scores + (size_t)chunk * 128;
#pragma unroll
                for (int mf = 0; mf < 2; mf++) {
                    int row = warpM * 32 + mf * 16 + g;
                    so[row]     = out_lo[mf] + sp[par * 128 + row]     + b2v;
                    so[row + 8] = out_hi[mf] + sp[par * 128 + row + 8] + b2v;
                }
            }
        }
    }
}

// -------- cost: C[n,i,j] = dot(f[n,i,j,:], f[n,j,i,:]); symmetric --------
__global__ void cost_kernel(const float* __restrict__ f) {
    int n = blockIdx.y;
    int gw = blockIdx.x * 8 + (threadIdx.x >> 5);
    int lane = threadIdx.x & 31;
    const float* fn = f + (size_t)n * LL * LL * HH;
    float* C = g_K + (size_t)n * LL * LL;
    float lmax = 0.0f;
    for (int a = gw; a < LL * LL; a += 512) {
        int i = a >> 8, j = a & 255;
        if (j < i) continue;
        float4 x = *((const float4*)(fn + (size_t)(i * LL + j) * HH) + lane);
        float4 y = *((const float4*)(fn + (size_t)(j * LL + i) * HH) + lane);
        float s = x.x * y.x + x.y * y.y + x.z * y.z + x.w * y.w;
#pragma unroll
        for (int o = 16; o > 0; o >>= 1) s += __shfl_xor_sync(0xffffffffu, s, o);
        if (lane == 0) {
            C[i * LL + j] = s;
            C[j * LL + i] = s;
            lmax = fmaxf(lmax, fabsf(s));
        }
    }
    if (lane == 0) atomicMax(&g_maxabs[n], __float_as_uint(lmax));
}

// -------- K = exp(-LAM*Cn), KM = K*Cn --------
__global__ void kexp_kernel() {
    int idx = blockIdx.x * blockDim.x + threadIdx.x;
    int n = idx >> 16;
    float mx = __uint_as_float(g_maxabs[n]);
    float cn = g_K[idx] / (mx + EPSF);
    float k = expf(-LAMF * cn);
    g_K[idx]  = k;
    g_KM[idx] = k * cn;
}

// -------- rT: softmax rows, transposed --------
__global__ void softmaxT_kernel(const float* __restrict__ scores) {
    __shared__ float sh[32][257];
    int blk = blockIdx.x;
    int n  = blk >> 3;
    int r0 = (blk & 7) << 5;
    int tid = threadIdx.x;
    int wid = tid >> 5, lane = tid & 31;
    const float* S = scores + ((size_t)n * 256 + r0) * 256;
#pragma unroll
    for (int s4 = 0; s4 < 4; s4++) {
        int rl = wid + 8 * s4;
        const float* row = S + rl * 256;
        float4 v0 = *(const float4*)(row + lane * 4);
        float4 v1 = *(const float4*)(row + 128 + lane * 4);
        float m = fmaxf(fmaxf(fmaxf(v0.x, v0.y), fmaxf(v0.z, v0.w)),
                        fmaxf(fmaxf(v1.x, v1.y), fmaxf(v1.z, v1.w)));
#pragma unroll
        for (int o = 16; o > 0; o >>= 1) m = fmaxf(m, __shfl_xor_sync(0xffffffffu, m, o));
        float e[8];
        e[0] = expf(v0.x - m); e[1] = expf(v0.y - m);
        e[2] = expf(v0.z - m); e[3] = expf(v0.w - m);
        e[4] = expf(v1.x - m); e[5] = expf(v1.y - m);
        e[6] = expf(v1.z - m); e[7] = expf(v1.w - m);
        float sum = e[0]+e[1]+e[2]+e[3]+e[4]+e[5]+e[6]+e[7];
#pragma unroll
        for (int o = 16; o > 0; o >>= 1) sum += __shfl_xor_sync(0xffffffffu, sum, o);
        float inv = 1.0f / sum;
#pragma unroll
        for (int q = 0; q < 4; q++) sh[rl][lane * 4 + q]       = e[q] * inv;
#pragma unroll
        for (int q = 0; q < 4; q++) sh[rl][128 + lane * 4 + q] = e[4 + q] * inv;
    }
    __syncthreads();
    int rloc = tid & 31, cb = tid >> 5;
    float* O = g_rT + (size_t)n * 65536 + r0;
#pragma unroll
    for (int s = 0; s < 32; s++) {
        int col = cb + 8 * s;
        O[(size_t)col * 256 + rloc] = sh[rloc][col];
    }
}

// -------- cT: (head+eps)/rowsum, transposed --------
__global__ void normT_kernel(const float* __restrict__ head) {
    __shared__ float sh[32][257];
    int blk = blockIdx.x;
    int n  = blk >> 3;
    int r0 = (blk & 7) << 5;
    int tid = threadIdx.x;
    int wid = tid >> 5, lane = tid & 31;
    const float* S = head + ((size_t)n * 256 + r0) * 256;
#pragma unroll
    for (int s4 = 0; s4 < 4; s4++) {
        int rl = wid + 8 * s4;
        const float* row = S + rl * 256;
        float4 v0 = *(const float4*)(row + lane * 4);
        float4 v1 = *(const float4*)(row + 128 + lane * 4);
        float e[8] = { v0.x + EPSF, v0.y + EPSF, v0.z + EPSF, v0.w + EPSF,
                       v1.x + EPSF, v1.y + EPSF, v1.z + EPSF, v1.w + EPSF };
        float sum = e[0]+e[1]+e[2]+e[3]+e[4]+e[5]+e[6]+e[7];
#pragma unroll
        for (int o = 16; o > 0; o >>= 1) sum += __shfl_xor_sync(0xffffffffu, sum, o);
        float inv = 1.0f / sum;
#pragma unroll
        for (int q = 0; q < 4; q++) sh[rl][lane * 4 + q]       = e[q] * inv;
#pragma unroll
        for (int q = 0; q < 4; q++) sh[rl][128 + lane * 4 + q] = e[4 + q] * inv;
    }
    __syncthreads();
    int rloc = tid & 31, cb = tid >> 5;
    float* O = g_cT + (size_t)n * 65536 + r0;
#pragma unroll
    for (int s = 0; s < 32; s++) {
        int col = cb + 8 * s;
        O[(size_t)col * 256 + rloc] = sh[rloc][col];
    }
}

// -------- Sinkhorn step: Out = Numer / (K @ X + eps) --------
__global__ void __launch_bounds__(256) gemm_div_kernel(int phase) {
    __shared__ float As[16][65];
    __shared__ float Bs[16][64];
    const float* X  = phase ? g_B  : g_U;
    const float* Nm = phase ? g_rT : g_cT;
    float* O        = phase ? g_U  : g_B;
    int n = blockIdx.z;
    const float* A  = g_K + (size_t)n * 65536;
    const float* Xn = X   + (size_t)n * 65536;
    int i0 = blockIdx.y * 64, c0 = blockIdx.x * 64;
    int tid = threadIdx.x;
    int tx = tid & 15, ty = tid >> 4;
    float acc[4][4];
#pragma unroll
    for (int i = 0; i < 4; i++)
#pragma unroll
        for (int j = 0; j < 4; j++) acc[i][j] = 0.0f;

    int am = tid >> 2, akq = (tid & 3) * 4;
    int bk = tid >> 4, bcq = (tid & 15) * 4;

    for (int kk = 0; kk < 256; kk += 16) {
        float4 av = *(const float4*)(A + (size_t)(i0 + am) * 256 + kk + akq);
        As[akq][am] = av.x; As[akq+1][am] = av.y; As[akq+2][am] = av.z; As[akq+3][am] = av.w;
        *(float4*)&Bs[bk][bcq] = *(const float4*)(Xn + (size_t)(kk + bk) * 256 + c0 + bcq);
        __syncthreads();
#pragma unroll
        for (int k = 0; k < 16; k++) {
            float4 b = *(float4*)&Bs[k][tx * 4];
            float a0 = As[k][ty], a1 = As[k][ty+16], a2 = As[k][ty+32], a3 = As[k][ty+48];
            acc[0][0]+=a0*b.x; acc[0][1]+=a0*b.y; acc[0][2]+=a0*b.z; acc[0][3]+=a0*b.w;
            acc[1][0]+=a1*b.x; acc[1][1]+=a1*b.y; acc[1][2]+=a1*b.z; acc[1][3]+=a1*b.w;
            acc[2][0]+=a2*b.x; acc[2][1]+=a2*b.y; acc[2][2]+=a2*b.z; acc[2][3]+=a2*b.w;
            acc[3][0]+=a3*b.x; acc[3][1]+=a3*b.y; acc[3][2]+=a3*b.z; acc[3][3]+=a3*b.w;
        }
        __syncthreads();
    }
#pragma unroll
    for (int i = 0; i < 4; i++) {
        size_t off = (size_t)n * 65536 + (size_t)(i0 + ty + 16 * i) * 256 + c0 + tx * 4;
        float4 nm = *(const float4*)(Nm + off);
        float4 o;
        o.x = nm.x / (acc[i][0] + EPSF);
        o.y = nm.y / (acc[i][1] + EPSF);
        o.z = nm.z / (acc[i][2] + EPSF);
        o.w = nm.w / (acc[i][3] + EPSF);
        *(float4*)(O + off) = o;
    }
}

// -------- final: loss += sum( U .* (KM @ V) ) --------
__global__ void __launch_bounds__(256) gemm_dot_kernel(float* __restrict__ loss) {
    __shared__ float As[16][65];
    __shared__ float Bs[16][64];
    __shared__ float red[8];
    int n = blockIdx.z;
    const float* A  = g_KM + (size_t)n * 65536;
    const float* Xn = g_B  + (size_t)n * 65536;
    int i0 = blockIdx.y * 64, c0 = blockIdx.x * 64;
    int tid = threadIdx.x;
    int tx = tid & 15, ty = tid >> 4;
    float acc[4][4];
#pragma unroll
    for (int i = 0; i < 4; i++)
#pragma unroll
        for (int j = 0; j < 4; j++) acc[i][j] = 0.0f;

    int am = tid >> 2, akq = (tid & 3) * 4;
    int bk = tid >> 4, bcq = (tid & 15) * 4;

    for (int kk = 0; kk < 256; kk += 16) {
        float4 av = *(const float4*)(A + (size_t)(i0 + am) * 256 + kk + akq);
        As[akq][am] = av.x; As[akq+1][am] = av.y; As[akq+2][am] = av.z; As[akq+3][am] = av.w;
        *(float4*)&Bs[bk][bcq] = *(const float4*)(Xn + (size_t)(kk + bk) * 256 + c0 + bcq);
        __syncthreads();
#pragma unroll
        for (int k = 0; k < 16; k++) {
            float4 b = *(float4*)&Bs[k][tx * 4];
            float a0 = As[k][ty], a1 = As[k][ty+16], a2 = As[k][ty+32], a3 = As[k][ty+48];
            acc[0][0]+=a0*b.x; acc[0][1]+=a0*b.y; acc[0][2]+=a0*b.z; acc[0][3]+=a0*b.w;
            acc[1][0]+=a1*b.x; acc[1][1]+=a1*b.y; acc[1][2]+=a1*b.z; acc[1][3]+=a1*b.w;
            acc[2][0]+=a2*b.x; acc[2][1]+=a2*b.y; acc[2][2]+=a2*b.z; acc[2][3]+=a2*b.w;
            acc[3][0]+=a3*b.x; acc[3][1]+=a3*b.y; acc[3][2]+=a3*b.z; acc[3][3]+=a3*b.w;
        }
        __syncthreads();
    }
    float s = 0.0f;
#pragma unroll
    for (int i = 0; i < 4; i++) {
        size_t off = (size_t)n * 65536 + (size_t)(i0 + ty + 16 * i) * 256 + c0 + tx * 4;
        float4 u = *(const float4*)(g_U + off);
        s += u.x * acc[i][0] + u.y * acc[i][1] + u.z * acc[i][2] + u.w * acc[i][3];
    }
    int wid = tid >> 5, lane = tid & 31;
#pragma unroll
    for (int o = 16; o > 0; o >>= 1) s += __shfl_xor_sync(0xffffffffu, s, o);
    if (lane == 0) red[wid] = s;
    __syncthreads();
    if (tid == 0) {
        float t = 0.0f;
#pragma unroll
        for (int w = 0; w < 8; w++) t += red[w];
        atomicAdd(loss, t);
    }
}

extern "C" void kernel_launch(void* const* d_in, const int* in_sizes, int n_in,
                              void* d_out, int out_size)
{
    const float* f    = (const float*)d_in[0];
    const float* head = (const float*)d_in[1];
    const float* W1   = (const float*)d_in[2];
    const float* b1   = (const float*)d_in[3];
    const float* W2   = (const float*)d_in[4];
    const float* b2   = (const float*)d_in[5];
    float* out    = (float*)d_out;
    float* scores = out;
    float* loss   = out + (out_size - 1);

    cudaFuncSetAttribute(mlp_mma_kernel, cudaFuncAttributeMaxDynamicSharedMemorySize, MLP_SMEM);

    init_kernel<<<NARC / 256, 256>>>(loss);
    prep_w_kernel<<<64, 256>>>(W1);
    mlp_mma_kernel<<<MLP_GRID, 384, MLP_SMEM>>>(f, b1, W2, b2, scores);
    cost_kernel<<<dim3(64, NS), 256>>>(f);
    kexp_kernel<<<NARC / 256, 256>>>();
    softmaxT_kernel<<<128, 256>>>(scores);
    normT_kernel<<<128, 256>>>(head);
    for (int it = 0; it < 20; ++it) {
        gemm_div_kernel<<<dim3(4, 4, NS), 256>>>(0);
        gemm_div_kernel<<<dim3(4, 4, NS), 256>>>(1);
    }
    gemm_div_kernel<<<dim3(4, 4, NS), 256>>>(0);
    gemm_dot_kernel<<<dim3(4, 4, NS), 256>>>(loss);
}

// round 4
// speedup vs baseline: 2.8125x; 2.0604x over previous
#include <cuda_runtime.h>
#include <cuda_bf16.h>
#include <math.h>
#include <stdint.h>

#define NS   16
#define LL   256
#define HH   128
#define LAMF 20.0f
#define EPSF 1e-8f
#define NARC (NS * LL * LL)   // 1,048,576
#define NCHUNK 8192
#define MLP_GRID 148

// -------- scratch (allocation-free: device globals) --------
__device__ __align__(16) float g_C [NARC];                 // cost C staging
__device__ __align__(16) float g_rT[NARC];                 // [n][support][problem]
__device__ __align__(16) float g_cT[NARC];
__device__ unsigned int g_maxabs[NS];
__device__ __align__(16) unsigned int g_Whi[8704];
__device__ __align__(16) unsigned int g_Wlo[8704];
// K/KM split bf16, MMA-A-fragment permuted layout (16B per (tile,lane))
__device__ __align__(16) __nv_bfloat16 g_Kph [NARC];
__device__ __align__(16) __nv_bfloat16 g_Kpl [NARC];
__device__ __align__(16) __nv_bfloat16 g_KMph[NARC];
__device__ __align__(16) __nv_bfloat16 g_KMpl[NARC];

// ================= PTX helpers (baseline sm_103) =================
__device__ __forceinline__ uint32_t smem_u32(const void* p) {
    uint32_t a;
    asm("{ .reg .u64 t; cvta.to.shared.u64 t, %1; cvt.u32.u64 %0, t; }" : "=r"(a) : "l"(p));
    return a;
}
#define MBAR_INIT(addr, cnt) \
    asm volatile("mbarrier.init.shared.b64 [%0], %1;" :: "r"(addr), "r"(cnt) : "memory")
#define MBAR_ARRIVE(addr) \
    asm volatile("mbarrier.arrive.shared.b64 _, [%0];" :: "r"(addr) : "memory")
#define MBAR_WAIT(addr, ph) do { \
    uint32_t _m = (addr); uint32_t _p = (ph); uint32_t _d; \
    asm volatile("{\n\t.reg .pred p;\n\tmbarrier.try_wait.parity.acquire.cta.shared::cta.b64 p, [%1], %2;\n\tselp.b32 %0, 1, 0, p;\n\t}" \
        : "=r"(_d) : "r"(_m), "r"(_p) : "memory"); \
    if (!_d) { \
        asm volatile("{\n\t.reg .pred P1;\n\tWL_%=:\n\tmbarrier.try_wait.parity.acquire.cta.shared::cta.b64 P1, [%0], %1, 0x989680;\n\t@P1 bra.uni WD_%=;\n\tbra.uni WL_%=;\n\tWD_%=:\n\t}" \
            :: "r"(_m), "r"(_p) : "memory"); \
    } } while (0)
#define LDSM_X4(r, addr) \
    asm volatile("ldmatrix.sync.aligned.m8n8.x4.shared.b16 {%0,%1,%2,%3}, [%4];" \
        : "=r"((r)[0]), "=r"((r)[1]), "=r"((r)[2]), "=r"((r)[3]) : "r"(addr))
#define LDSM_X4T(r, addr) \
    asm volatile("ldmatrix.sync.aligned.m8n8.x4.trans.shared.b16 {%0,%1,%2,%3}, [%4];" \
        : "=r"((r)[0]), "=r"((r)[1]), "=r"((r)[2]), "=r"((r)[3]) : "r"(addr))
#define MMA_BF16(d, a, b) \
    asm volatile("mma.sync.aligned.m16n8k16.row.col.f32.bf16.bf16.f32 " \
        "{%0,%1,%2,%3}, {%4,%5,%6,%7}, {%8,%9}, {%0,%1,%2,%3};" \
        : "+f"((d)[0]), "+f"((d)[1]), "+f"((d)[2]), "+f"((d)[3]) \
        : "r"((a)[0]), "r"((a)[1]), "r"((a)[2]), "r"((a)[3]), "r"((b)[0]), "r"((b)[1]))
__device__ __forceinline__ void sts32(uint32_t addr, uint32_t v) {
    asm volatile("st.shared.b32 [%0], %1;" :: "r"(addr), "r"(v) : "memory");
}
__device__ __forceinline__ float lds32f(uint32_t addr) {
    float v; asm volatile("ld.shared.f32 %0, [%1];" : "=f"(v) : "r"(addr)); return v;
}
__device__ __forceinline__ void sts32f(uint32_t addr, float v) {
    asm volatile("st.shared.f32 [%0], %1;" :: "r"(addr), "f"(v) : "memory");
}
__device__ __forceinline__ uint32_t pack_bf16(__nv_bfloat16 a, __nv_bfloat16 b) {
    __nv_bfloat162 p = __halves2bfloat162(a, b);
    return *reinterpret_cast<uint32_t*>(&p);
}
__device__ __forceinline__ uint32_t split_pack_hi(float a, float b,
                                                  float& ra, float& rb) {
    __nv_bfloat16 ha = __float2bfloat16(a), hb = __float2bfloat16(b);
    ra = a - __bfloat162float(ha);
    rb = b - __bfloat162float(hb);
    return pack_bf16(ha, hb);
}
__device__ __forceinline__ float ftanh(float x) {
    float e = __expf(2.0f * x);
    return 1.0f - __fdividef(2.0f, e + 1.0f);
}

// -------- init --------
__global__ void init_kernel(float* __restrict__ loss) {
    int idx = threadIdx.x;
    if (idx < NS) g_maxabs[idx] = 0u;
    if (idx == 0) *loss = 0.0f;
}

// -------- prep W1 split bf16 [k][n] pitch 136 --------
__global__ void prep_w_kernel(const float* __restrict__ W1) {
    int idx = blockIdx.x * 256 + threadIdx.x;
    int k = idx >> 7, n = idx & 127;
    float x = W1[idx];
    __nv_bfloat16 h = __float2bfloat16(x);
    float l = x - __bfloat162float(h);
    int off = k * 136 + n;
    ((__nv_bfloat16*)g_Whi)[off] = h;
    ((__nv_bfloat16*)g_Wlo)[off] = __float2bfloat16(l);
}

// ============ MLP via mma.sync bf16 (unchanged from R3, passing) ============
#define PITCHB  272
#define ATILE   34816
#define B1S_OFF 1088
#define W2S_OFF 1600
#define WHI_OFF 2176
#define WLO_OFF 36992
#define A_OFF   71808
#define SP_OFF  64
#define MLP_SMEM 211072

__global__ void __launch_bounds__(384, 1) mlp_mma_kernel(
    const float* __restrict__ f,  const float* __restrict__ b1,
    const float* __restrict__ W2, const float* __restrict__ b2,
    float* __restrict__ scores)
{
    extern __shared__ __align__(1024) char smem[];
    const uint32_t sb = smem_u32(smem);
    const int tid = threadIdx.x;

    if (tid == 0) {
        MBAR_INIT(sb + 16, 128); MBAR_INIT(sb + 24, 128);
        MBAR_INIT(sb + 32, 256); MBAR_INIT(sb + 40, 256);
    }
    for (int i = tid; i < 8704; i += 384) {
        ((uint32_t*)(smem + WHI_OFF))[i] = g_Whi[i];
        ((uint32_t*)(smem + WLO_OFF))[i] = g_Wlo[i];
    }
    if (tid < 128) {
        ((float*)(smem + B1S_OFF))[tid] = b1[tid];
        ((float*)(smem + W2S_OFF))[tid] = W2[tid];
    }
    __syncthreads();

    if (tid >= 256) {
        const int ptid = tid - 256;
        int lc = 0;
        for (int chunk = blockIdx.x; chunk < NCHUNK; chunk += MLP_GRID, ++lc) {
            const int s = lc & 1;
            if (lc >= 2) MBAR_WAIT(sb + 32 + s * 8, ((lc >> 1) - 1) & 1);
            const float4* src = (const float4*)(f + (size_t)chunk * 16384);
            char* ahi = smem + A_OFF + s * (2 * ATILE);
            char* alo = ahi + ATILE;
#pragma unroll 4
            for (int q = 0; q < 32; q++) {
                int idx = q * 128 + ptid;
                float4 v = __ldg(src + idx);
                int row = idx >> 5, colq = (idx & 31) << 2;
                int off = row * PITCHB + colq * 2;
                float l0, l1, l2, l3;
                uint32_t h01 = split_pack_hi(v.x, v.y, l0, l1);
                uint32_t h23 = split_pack_hi(v.z, v.w, l2, l3);
                *(uint2*)(ahi + off) = make_uint2(h01, h23);
                *(uint2*)(alo + off) = make_uint2(
                    pack_bf16(__float2bfloat16(l0), __float2bfloat16(l1)),
                    pack_bf16(__float2bfloat16(l2), __float2bfloat16(l3)));
            }
            MBAR_ARRIVE(sb + 16 + s * 8);
        }
    } else {
        const int lane = tid & 31, wid = tid >> 5;
        const int warpM = wid >> 1, warpN = wid & 1;
        const int t = lane & 3, g = lane >> 2;
        const int lr = lane & 15, lh = lane >> 4;
        const float b2v = __ldg(b2);
        const float* sh_b1 = (const float*)(smem + B1S_OFF);
        const float* sh_w2 = (const float*)(smem + W2S_OFF);
        float* sp = (float*)(smem + SP_OFF);
        const uint32_t a_off = (uint32_t)((warpM * 32 + lr) * PITCHB + lh * 16);
        const uint32_t b_off = (uint32_t)(lr * PITCHB + (warpN * 64 + lh * 8) * 2);

        int lc = 0;
        for (int chunk = blockIdx.x; chunk < NCHUNK; chunk += MLP_GRID, ++lc) {
            const int s = lc & 1;
            MBAR_WAIT(sb + 16 + s * 8, (lc >> 1) & 1);
            const uint32_t sa_hi = sb + A_OFF + s * (2 * ATILE);
            const uint32_t sa_lo = sa_hi + ATILE;

            float D[2][8][4];
#pragma unroll
            for (int i = 0; i < 2; i++)
#pragma unroll
                for (int j = 0; j < 8; j++)
#pragma unroll
                    for (int q = 0; q < 4; q++) D[i][j][q] = 0.0f;

#pragma unroll
            for (int ks = 0; ks < 8; ks++) {
                uint32_t ah0[4], ah1[4], al0[4], al1[4];
                LDSM_X4(ah0, sa_hi + a_off + ks * 32);
                LDSM_X4(ah1, sa_hi + a_off + 16 * PITCHB + ks * 32);
                LDSM_X4(al0, sa_lo + a_off + ks * 32);
                LDSM_X4(al1, sa_lo + a_off + 16 * PITCHB + ks * 32);
                uint32_t bh[8][2], bl[8][2];
#pragma unroll
                for (int p = 0; p < 4; p++) {
                    uint32_t r[4];
                    LDSM_X4T(r, sb + WHI_OFF + b_off + ks * (16 * PITCHB) + p * 32);
                    bh[2*p][0] = r[0]; bh[2*p][1] = r[1];
                    bh[2*p+1][0] = r[2]; bh[2*p+1][1] = r[3];
                    LDSM_X4T(r, sb + WLO_OFF + b_off + ks * (16 * PITCHB) + p * 32);
                    bl[2*p][0] = r[0]; bl[2*p][1] = r[1];
                    bl[2*p+1][0] = r[2]; bl[2*p+1][1] = r[3];
                }
#pragma unroll
                for (int nf = 0; nf < 8; nf++) {
                    MMA_BF16(D[0][nf], ah0, bh[nf]);
                    MMA_BF16(D[1][nf], ah1, bh[nf]);
                    MMA_BF16(D[0][nf], al0, bh[nf]);
                    MMA_BF16(D[1][nf], al1, bh[nf]);
                    MMA_BF16(D[0][nf], ah0, bl[nf]);
                    MMA_BF16(D[1][nf], ah1, bl[nf]);
                }
            }
            MBAR_ARRIVE(sb + 32 + s * 8);

            float out_lo[2], out_hi[2];
#pragma unroll
            for (int mf = 0; mf < 2; mf++) {
                float plo = 0.0f, phi = 0.0f;
#pragma unroll
                for (int nf = 0; nf < 8; nf++) {
                    int col = warpN * 64 + nf * 8 + 2 * t;
                    float b1a = sh_b1[col], b1b = sh_b1[col + 1];
                    float w2a = sh_w2[col], w2b = sh_w2[col + 1];
                    plo += ftanh(D[mf][nf][0] + b1a) * w2a + ftanh(D[mf][nf][1] + b1b) * w2b;
                    phi += ftanh(D[mf][nf][2] + b1a) * w2a + ftanh(D[mf][nf][3] + b1b) * w2b;
                }
                plo += __shfl_xor_sync(0xffffffffu, plo, 1);
                plo += __shfl_xor_sync(0xffffffffu, plo, 2);
                phi += __shfl_xor_sync(0xffffffffu, phi, 1);
                phi += __shfl_xor_sync(0xffffffffu, phi, 2);
                out_lo[mf] = plo; out_hi[mf] = phi;
            }
            const int par = lc & 1;
            if (warpN == 0 && t == 0) {
#pragma unroll
                for (int mf = 0; mf < 2; mf++) {
                    int row = warpM * 32 + mf * 16 + g;
                    sp[par * 128 + row]     = out_lo[mf];
                    sp[par * 128 + row + 8] = out_hi[mf];
                }
            }
            asm volatile("bar.sync 1, 256;" ::: "memory");
            if (warpN == 1 && t == 0) {
                float* so = scores + (size_t)chunk * 128;
#pragma unroll
                for (int mf = 0; mf < 2; mf++) {
                    int row = warpM * 32 + mf * 16 + g;
                    so[row]     = out_lo[mf] + sp[par * 128 + row]     + b2v;
                    so[row + 8] = out_hi[mf] + sp[par * 128 + row + 8] + b2v;
                }
            }
        }
    }
}

// -------- cost: C[n,i,j] = dot(f[n,i,j,:], f[n,j,i,:]); symmetric --------
__global__ void cost_kernel(const float* __restrict__ f) {
    int n = blockIdx.y;
    int gw = blockIdx.x * 8 + (threadIdx.x >> 5);
    int lane = threadIdx.x & 31;
    const float* fn = f + (size_t)n * LL * LL * HH;
    float* C = g_C + (size_t)n * LL * LL;
    float lmax = 0.0f;
    for (int a = gw; a < LL * LL; a += 512) {
        int i = a >> 8, j = a & 255;
        if (j < i) continue;
        float4 x = *((const float4*)(fn + (size_t)(i * LL + j) * HH) + lane);
        float4 y = *((const float4*)(fn + (size_t)(j * LL + i) * HH) + lane);
        float s = x.x * y.x + x.y * y.y + x.z * y.z + x.w * y.w;
#pragma unroll
        for (int o = 16; o > 0; o >>= 1) s += __shfl_xor_sync(0xffffffffu, s, o);
        if (lane == 0) {
            C[i * LL + j] = s;
            C[j * LL + i] = s;
            lmax = fmaxf(lmax, fabsf(s));
        }
    }
    if (lane == 0) atomicMax(&g_maxabs[n], __float_as_uint(lmax));
}

// -------- kexp: K=exp(-LAM*Cn), KM=K*Cn -> split bf16, MMA-A-permuted --------
__global__ void kexp_kernel() {
    int idx = blockIdx.x * blockDim.x + threadIdx.x;
    int n = idx >> 16;
    int r = (idx >> 8) & 255, k = idx & 255;
    float mx = __uint_as_float(g_maxabs[n]);
    float cn = g_C[idx] / (mx + EPSF);
    float kv = expf(-LAMF * cn);
    float km = kv * cn;
    int mt = r >> 4, rl = r & 15, kt = k >> 4, kl = k & 15;
    int T   = ((rl & 7) << 2) + ((kl & 7) >> 1);
    int reg = (rl >> 3) + ((kl >> 3) << 1);
    int pofs = (n << 16) + (((mt << 4) + kt) << 8) + (T << 3) + (reg << 1) + (kl & 1);
    __nv_bfloat16 kh = __float2bfloat16(kv);
    __nv_bfloat16 mh = __float2bfloat16(km);
    g_Kph [pofs] = kh;
    g_Kpl [pofs] = __float2bfloat16(kv - __bfloat162float(kh));
    g_KMph[pofs] = mh;
    g_KMpl[pofs] = __float2bfloat16(km - __bfloat162float(mh));
}

// -------- rT: softmax rows, transposed [n][support][problem] --------
__global__ void softmaxT_kernel(const float* __restrict__ scores) {
    __shared__ float sh[32][257];
    int blk = blockIdx.x;
    int n  = blk >> 3;
    int r0 = (blk & 7) << 5;
    int tid = threadIdx.x;
    int wid = tid >> 5, lane = tid & 31;
    const float* S = scores + ((size_t)n * 256 + r0) * 256;
#pragma unroll
    for (int s4 = 0; s4 < 4; s4++) {
        int rl = wid + 8 * s4;
        const float* row = S + rl * 256;
        float4 v0 = *(const float4*)(row + lane * 4);
        float4 v1 = *(const float4*)(row + 128 + lane * 4);
        float m = fmaxf(fmaxf(fmaxf(v0.x, v0.y), fmaxf(v0.z, v0.w)),
                        fmaxf(fmaxf(v1.x, v1.y), fmaxf(v1.z, v1.w)));
#pragma unroll
        for (int o = 16; o > 0; o >>= 1) m = fmaxf(m, __shfl_xor_sync(0xffffffffu, m, o));
        float e[8];
        e[0] = expf(v0.x - m); e[1] = expf(v0.y - m);
        e[2] = expf(v0.z - m); e[3] = expf(v0.w - m);
        e[4] = expf(v1.x - m); e[5] = expf(v1.y - m);
        e[6] = expf(v1.z - m); e[7] = expf(v1.w - m);
        float sum = e[0]+e[1]+e[2]+e[3]+e[4]+e[5]+e[6]+e[7];
#pragma unroll
        for (int o = 16; o > 0; o >>= 1) sum += __shfl_xor_sync(0xffffffffu, sum, o);
        float inv = 1.0f / sum;
#pragma unroll
        for (int q = 0; q < 4; q++) sh[rl][lane * 4 + q]       = e[q] * inv;
#pragma unroll
        for (int q = 0; q < 4; q++) sh[rl][128 + lane * 4 + q] = e[4 + q] * inv;
    }
    __syncthreads();
    int rloc = tid & 31, cb = tid >> 5;
    float* O = g_rT + (size_t)n * 65536 + r0;
#pragma unroll
    for (int s = 0; s < 32; s++) {
        int col = cb + 8 * s;
        O[(size_t)col * 256 + rloc] = sh[rloc][col];
    }
}

// -------- cT: (head+eps)/rowsum, transposed --------
__global__ void normT_kernel(const float* __restrict__ head) {
    __shared__ float sh[32][257];
    int blk = blockIdx.x;
    int n  = blk >> 3;
    int r0 = (blk & 7) << 5;
    int tid = threadIdx.x;
    int wid = tid >> 5, lane = tid & 31;
    const float* S = head + ((size_t)n * 256 + r0) * 256;
#pragma unroll
    for (int s4 = 0; s4 < 4; s4++) {
        int rl = wid + 8 * s4;
        const float* row = S + rl * 256;
        float4 v0 = *(const float4*)(row + lane * 4);
        float4 v1 = *(const float4*)(row + 128 + lane * 4);
        float e[8] = { v0.x + EPSF, v0.y + EPSF, v0.z + EPSF, v0.w + EPSF,
                       v1.x + EPSF, v1.y + EPSF, v1.z + EPSF, v1.w + EPSF };
        float sum = e[0]+e[1]+e[2]+e[3]+e[4]+e[5]+e[6]+e[7];
#pragma unroll
        for (int o = 16; o > 0; o >>= 1) sum += __shfl_xor_sync(0xffffffffu, sum, o);
        float inv = 1.0f / sum;
#pragma unroll
        for (int q = 0; q < 4; q++) sh[rl][lane * 4 + q]       = e[q] * inv;
#pragma unroll
        for (int q = 0; q < 4; q++) sh[rl][128 + lane * 4 + q] = e[4 + q] * inv;
    }
    __syncthreads();
    int rloc = tid & 31, cb = tid >> 5;
    float* O = g_cT + (size_t)n * 65536 + r0;
#pragma unroll
    for (int s = 0; s < 32; s++) {
        int col = cb + 8 * s;
        O[(size_t)col * 256 + rloc] = sh[rloc][col];
    }
}

// ============ fused Sinkhorn: 20 iters + loss in ONE kernel ============
// grid 128 = 16 samples x 8 col-blocks of 32 problems. No inter-CTA comm.
// smem: XHI 0 (20480) | XLO 20480 (20480) | UN 40960 (33792) | CN 74752 (33792)
//       UF 108544 (33792) | RED 142336 (64)
#define SK_XHI 0
#define SK_XLO 20480
#define SK_UN  40960
#define SK_CN  74752
#define SK_UF  108544
#define SK_RED 142336
#define SK_SMEM 142400

// One phase: D = A @ X (split bf16 HMMA), newX = numer/(D+eps), re-split in place.
template<bool STORE_U>
__device__ __noinline__ void sink_phase(
    const uint4* __restrict__ Ah, const uint4* __restrict__ Al,
    uint32_t xhi, uint32_t xlo, uint32_t nmb, uint32_t ufb, int w, int lane)
{
    float D[2][4][4];
#pragma unroll
    for (int i = 0; i < 2; i++)
#pragma unroll
        for (int j = 0; j < 4; j++)
#pragma unroll
            for (int q = 0; q < 4; q++) D[i][j][q] = 0.0f;

    const int lr = lane & 15, lh = lane >> 4;
    const uint32_t bhb = xhi + lr * 80 + lh * 16;
    const uint32_t blb = xlo + lr * 80 + lh * 16;
#pragma unroll 4
    for (int kt = 0; kt < 16; kt++) {
        uint4 ah0 = Ah[(size_t)(w * 32 + kt) * 32 + lane];
        uint4 ah1 = Ah[(size_t)(w * 32 + 16 + kt) * 32 + lane];
        uint4 al0 = Al[(size_t)(w * 32 + kt) * 32 + lane];
        uint4 al1 = Al[(size_t)(w * 32 + 16 + kt) * 32 + lane];
        uint32_t bh[4][2], bl[4][2], r[4];
        LDSM_X4T(r, bhb + kt * 1280);      bh[0][0]=r[0]; bh[0][1]=r[1]; bh[1][0]=r[2]; bh[1][1]=r[3];
        LDSM_X4T(r, bhb + kt * 1280 + 32); bh[2][0]=r[0]; bh[2][1]=r[1]; bh[3][0]=r[2]; bh[3][1]=r[3];
        LDSM_X4T(r, blb + kt * 1280);      bl[0][0]=r[0]; bl[0][1]=r[1]; bl[1][0]=r[2]; bl[1][1]=r[3];
        LDSM_X4T(r, blb + kt * 1280 + 32); bl[2][0]=r[0]; bl[2][1]=r[1]; bl[3][0]=r[2]; bl[3][1]=r[3];
#pragma unroll
        for (int nt = 0; nt < 4; nt++) {
            MMA_BF16(D[0][nt], ((uint32_t*)&ah0), bh[nt]);
            MMA_BF16(D[1][nt], ((uint32_t*)&ah1), bh[nt]);
            MMA_BF16(D[0][nt], ((uint32_t*)&al0), bh[nt]);
            MMA_BF16(D[1][nt], ((uint32_t*)&al1), bh[nt]);
            MMA_BF16(D[0][nt], ((uint32_t*)&ah0), bl[nt]);
            MMA_BF16(D[1][nt], ((uint32_t*)&ah1), bl[nt]);
        }
    }
    __syncthreads();   // all reads of X done
    const int rq = lane >> 2, cq = (lane & 3) * 2;
#pragma unroll
    for (int mt = 0; mt < 2; mt++) {
        int row = w * 32 + mt * 16 + rq;
#pragma unroll
        for (int nt = 0; nt < 4; nt++) {
            int col = nt * 8 + cq;
            float n0 = lds32f(nmb + (row * 33 + col) * 4);
            float n1 = lds32f(nmb + (row * 33 + col + 1) * 4);
            float n2 = lds32f(nmb + ((row + 8) * 33 + col) * 4);
            float n3 = lds32f(nmb + ((row + 8) * 33 + col + 1) * 4);
            float o0 = n0 / (D[mt][nt][0] + EPSF);
            float o1 = n1 / (D[mt][nt][1] + EPSF);
            float o2 = n2 / (D[mt][nt][2] + EPSF);
            float o3 = n3 / (D[mt][nt][3] + EPSF);
            float l0, l1, l2, l3;
            uint32_t h01 = split_pack_hi(o0, o1, l0, l1);
            uint32_t h23 = split_pack_hi(o2, o3, l2, l3);
            sts32(xhi + row * 80 + col * 2, h01);
            sts32(xhi + (row + 8) * 80 + col * 2, h23);
            sts32(xlo + row * 80 + col * 2,
                  pack_bf16(__float2bfloat16(l0), __float2bfloat16(l1)));
            sts32(xlo + (row + 8) * 80 + col * 2,
                  pack_bf16(__float2bfloat16(l2), __float2bfloat16(l3)));
            if (STORE_U) {
                sts32f(ufb + (row * 33 + col) * 4, o0);
                sts32f(ufb + (row * 33 + col + 1) * 4, o1);
                sts32f(ufb + ((row + 8) * 33 + col) * 4, o2);
                sts32f(ufb + ((row + 8) * 33 + col + 1) * 4, o3);
            }
        }
    }
    __syncthreads();   // newX visible
}

__global__ void __launch_bounds__(256, 1) sinkhorn_fused_kernel(float* __restrict__ loss)
{
    extern __shared__ __align__(16) char smem[];
    const uint32_t sb = smem_u32(smem);
    const int tid = threadIdx.x, lane = tid & 31, w = tid >> 5;
    const int n = blockIdx.x >> 3, c0 = (blockIdx.x & 7) * 32;

    // load numerator blocks (fp32, pitch 33)
    const float* rTn = g_rT + (size_t)n * 65536 + c0;
    const float* cTn = g_cT + (size_t)n * 65536 + c0;
    float* UN = (float*)(smem + SK_UN);
    float* CN = (float*)(smem + SK_CN);
    for (int i = tid; i < 8192; i += 256) {
        int r = i >> 5, c = i & 31;
        UN[r * 33 + c] = rTn[(size_t)r * 256 + c];
        CN[r * 33 + c] = cTn[(size_t)r * 256 + c];
    }
    // X = u0 = 1/256 (exact in bf16, lo = 0)
    const uint32_t HV = pack_bf16(__float2bfloat16(1.0f / 256.0f),
                                  __float2bfloat16(1.0f / 256.0f));
    for (int i = tid; i < 5120; i += 256) {
        ((uint32_t*)(smem + SK_XHI))[i] = HV;
        ((uint32_t*)(smem + SK_XLO))[i] = 0u;
    }
    __syncthreads();

    const uint4* Kh  = (const uint4*)g_Kph  + (size_t)n * 8192;
    const uint4* Kl  = (const uint4*)g_Kpl  + (size_t)n * 8192;
    const uint4* Mh  = (const uint4*)g_KMph + (size_t)n * 8192;
    const uint4* Ml  = (const uint4*)g_KMpl + (size_t)n * 8192;
    const uint32_t xhi = sb + SK_XHI, xlo = sb + SK_XLO;
    const uint32_t unb = sb + SK_UN, cnb = sb + SK_CN, ufb = sb + SK_UF;

#pragma unroll 1
    for (int it = 0; it < 19; it++) {
        sink_phase<false>(Kh, Kl, xhi, xlo, cnb, ufb, w, lane);   // b = cT/(K u)
        sink_phase<false>(Kh, Kl, xhi, xlo, unb, ufb, w, lane);   // u = rT/(K b)
    }
    sink_phase<false>(Kh, Kl, xhi, xlo, cnb, ufb, w, lane);
    sink_phase<true >(Kh, Kl, xhi, xlo, unb, ufb, w, lane);       // final u (fp32 kept)
    sink_phase<false>(Kh, Kl, xhi, xlo, cnb, ufb, w, lane);       // v

    // loss partial: sum uF .* (KM @ v)
    float D[2][4][4];
#pragma unroll
    for (int i = 0; i < 2; i++)
#pragma unroll
        for (int j = 0; j < 4; j++)
#pragma unroll
            for (int q = 0; q < 4; q++) D[i][j][q] = 0.0f;
    {
        const int lr = lane & 15, lh = lane >> 4;
        const uint32_t bhb = xhi + lr * 80 + lh * 16;
        const uint32_t blb = xlo + lr * 80 + lh * 16;
#pragma unroll 4
        for (int kt = 0; kt < 16; kt++) {
            uint4 ah0 = Mh[(size_t)(w * 32 + kt) * 32 + lane];
            uint4 ah1 = Mh[(size_t)(w * 32 + 16 + kt) * 32 + lane];
            uint4 al0 = Ml[(size_t)(w * 32 + kt) * 32 + lane];
            uint4 al1 = Ml[(size_t)(w * 32 + 16 + kt) * 32 + lane];
            uint32_t bh[4][2], bl[4][2], r[4];
            LDSM_X4T(r, bhb + kt * 1280);      bh[0][0]=r[0]; bh[0][1]=r[1]; bh[1][0]=r[2]; bh[1][1]=r[3];
            LDSM_X4T(r, bhb + kt * 1280 + 32); bh[2][0]=r[0]; bh[2][1]=r[1]; bh[3][0]=r[2]; bh[3][1]=r[3];
            LDSM_X4T(r, blb + kt * 1280);      bl[0][0]=r[0]; bl[0][1]=r[1]; bl[1][0]=r[2]; bl[1][1]=r[3];
            LDSM_X4T(r, blb + kt * 1280 + 32); bl[2][0]=r[0]; bl[2][1]=r[1]; bl[3][0]=r[2]; bl[3][1]=r[3];
#pragma unroll
            for (int nt = 0; nt < 4; nt++) {
                MMA_BF16(D[0][nt], ((uint32_t*)&ah0), bh[nt]);
                MMA_BF16(D[1][nt], ((uint32_t*)&ah1), bh[nt]);
                MMA_BF16(D[0][nt], ((uint32_t*)&al0), bh[nt]);
                MMA_BF16(D[1][nt], ((uint32_t*)&al1), bh[nt]);
                MMA_BF16(D[0][nt], ((uint32_t*)&ah0), bl[nt]);
                MMA_BF16(D[1][nt], ((uint32_t*)&ah1), bl[nt]);
            }
        }
    }
    float part = 0.0f;
    {
        const int rq = lane >> 2, cq = (lane & 3) * 2;
#pragma unroll
        for (int mt = 0; mt < 2; mt++) {
            int row = w * 32 + mt * 16 + rq;
#pragma unroll
            for (int nt = 0; nt < 4; nt++) {
                int col = nt * 8 + cq;
                part += lds32f(ufb + (row * 33 + col) * 4)       * D[mt][nt][0];
                part += lds32f(ufb + (row * 33 + col + 1) * 4)   * D[mt][nt][1];
                part += lds32f(ufb + ((row + 8) * 33 + col) * 4) * D[mt][nt][2];
                part += lds32f(ufb + ((row + 8) * 33 + col + 1) * 4) * D[mt][nt][3];
            }
        }
    }
#pragma unroll
    for (int o = 16; o > 0; o >>= 1) part += __shfl_xor_sync(0xffffffffu, part, o);
    float* RED = (float*)(smem + SK_RED);
    if (lane == 0) RED[w] = part;
    __syncthreads();
    if (tid == 0) {
        float t = 0.0f;
#pragma unroll
        for (int i = 0; i < 8; i++) t += RED[i];
        atomicAdd(loss, t);
    }
}

extern "C" void kernel_launch(void* const* d_in, const int* in_sizes, int n_in,
                              void* d_out, int out_size)
{
    const float* f    = (const float*)d_in[0];
    const float* head = (const float*)d_in[1];
    const float* W1   = (const float*)d_in[2];
    const float* b1   = (const float*)d_in[3];
    const float* W2   = (const float*)d_in[4];
    const float* b2   = (const float*)d_in[5];
    float* out    = (float*)d_out;
    float* scores = out;
    float* loss   = out + (out_size - 1);

    cudaFuncSetAttribute(mlp_mma_kernel, cudaFuncAttributeMaxDynamicSharedMemorySize, MLP_SMEM);
    cudaFuncSetAttribute(sinkhorn_fused_kernel, cudaFuncAttributeMaxDynamicSharedMemorySize, SK_SMEM);

    init_kernel<<<1, 256>>>(loss);
    prep_w_kernel<<<64, 256>>>(W1);
    mlp_mma_kernel<<<MLP_GRID, 384, MLP_SMEM>>>(f, b1, W2, b2, scores);
    cost_kernel<<<dim3(64, NS), 256>>>(f);
    kexp_kernel<<<NARC / 256, 256>>>();
    softmaxT_kernel<<<128, 256>>>(scores);
    normT_kernel<<<128, 256>>>(head);
    sinkhorn_fused_kernel<<<128, 256, SK_SMEM>>>(loss);
}

// round 5
// speedup vs baseline: 3.0190x; 1.0734x over previous
#include <cuda_runtime.h>
#include <cuda_bf16.h>
#include <cuda_fp16.h>
#include <math.h>
#include <stdint.h>

#define NS   16
#define LL   256
#define HH   128
#define LAMF 20.0f
#define EPSF 1e-8f
#define NARC (NS * LL * LL)   // 1,048,576
#define NCHUNK 8192
#define MLP_GRID 148

// -------- scratch (allocation-free: device globals) --------
__device__ __align__(16) float g_C [NARC];                 // cost C staging
__device__ __align__(16) float g_rT[NARC];                 // [n][support][problem]
__device__ __align__(16) float g_cT[NARC];
__device__ unsigned int g_maxabs[NS];
__device__ __align__(16) unsigned int g_Wh[8704];          // W1 fp16, padded [k][n] pitch 136
// K/KM split bf16, MMA-A-fragment permuted layout (16B per (tile,lane))
__device__ __align__(16) __nv_bfloat16 g_Kph [NARC];
__device__ __align__(16) __nv_bfloat16 g_Kpl [NARC];
__device__ __align__(16) __nv_bfloat16 g_KMph[NARC];
__device__ __align__(16) __nv_bfloat16 g_KMpl[NARC];

// ================= PTX helpers (baseline sm_103) =================
__device__ __forceinline__ uint32_t smem_u32(const void* p) {
    uint32_t a;
    asm("{ .reg .u64 t; cvta.to.shared.u64 t, %1; cvt.u32.u64 %0, t; }" : "=r"(a) : "l"(p));
    return a;
}
#define MBAR_INIT(addr, cnt) \
    asm volatile("mbarrier.init.shared.b64 [%0], %1;" :: "r"(addr), "r"(cnt) : "memory")
#define MBAR_ARRIVE(addr) \
    asm volatile("mbarrier.arrive.shared.b64 _, [%0];" :: "r"(addr) : "memory")
#define MBAR_WAIT(addr, ph) do { \
    uint32_t _m = (addr); uint32_t _p = (ph); uint32_t _d; \
    asm volatile("{\n\t.reg .pred p;\n\tmbarrier.try_wait.parity.acquire.cta.shared::cta.b64 p, [%1], %2;\n\tselp.b32 %0, 1, 0, p;\n\t}" \
        : "=r"(_d) : "r"(_m), "r"(_p) : "memory"); \
    if (!_d) { \
        asm volatile("{\n\t.reg .pred P1;\n\tWL_%=:\n\tmbarrier.try_wait.parity.acquire.cta.shared::cta.b64 P1, [%0], %1, 0x989680;\n\t@P1 bra.uni WD_%=;\n\tbra.uni WL_%=;\n\tWD_%=:\n\t}" \
            :: "r"(_m), "r"(_p) : "memory"); \
    } } while (0)
#define LDSM_X4(r, addr) \
    asm volatile("ldmatrix.sync.aligned.m8n8.x4.shared.b16 {%0,%1,%2,%3}, [%4];" \
        : "=r"((r)[0]), "=r"((r)[1]), "=r"((r)[2]), "=r"((r)[3]) : "r"(addr))
#define LDSM_X4T(r, addr) \
    asm volatile("ldmatrix.sync.aligned.m8n8.x4.trans.shared.b16 {%0,%1,%2,%3}, [%4];" \
        : "=r"((r)[0]), "=r"((r)[1]), "=r"((r)[2]), "=r"((r)[3]) : "r"(addr))
#define MMA_BF16(d, a, b) \
    asm volatile("mma.sync.aligned.m16n8k16.row.col.f32.bf16.bf16.f32 " \
        "{%0,%1,%2,%3}, {%4,%5,%6,%7}, {%8,%9}, {%0,%1,%2,%3};" \
        : "+f"((d)[0]), "+f"((d)[1]), "+f"((d)[2]), "+f"((d)[3]) \
        : "r"((a)[0]), "r"((a)[1]), "r"((a)[2]), "r"((a)[3]), "r"((b)[0]), "r"((b)[1]))
#define MMA_F16(d, a, b) \
    asm volatile("mma.sync.aligned.m16n8k16.row.col.f32.f16.f16.f32 " \
        "{%0,%1,%2,%3}, {%4,%5,%6,%7}, {%8,%9}, {%0,%1,%2,%3};" \
        : "+f"((d)[0]), "+f"((d)[1]), "+f"((d)[2]), "+f"((d)[3]) \
        : "r"((a)[0]), "r"((a)[1]), "r"((a)[2]), "r"((a)[3]), "r"((b)[0]), "r"((b)[1]))
__device__ __forceinline__ void sts32(uint32_t addr, uint32_t v) {
    asm volatile("st.shared.b32 [%0], %1;" :: "r"(addr), "r"(v) : "memory");
}
__device__ __forceinline__ float lds32f(uint32_t addr) {
    float v; asm volatile("ld.shared.f32 %0, [%1];" : "=f"(v) : "r"(addr)); return v;
}
__device__ __forceinline__ void sts32f(uint32_t addr, float v) {
    asm volatile("st.shared.f32 [%0], %1;" :: "r"(addr), "f"(v) : "memory");
}
__device__ __forceinline__ uint32_t pack_bf16(__nv_bfloat16 a, __nv_bfloat16 b) {
    __nv_bfloat162 p = __halves2bfloat162(a, b);
    return *reinterpret_cast<uint32_t*>(&p);
}
__device__ __forceinline__ uint32_t pack_h16(__half a, __half b) {
    __half2 p = __halves2half2(a, b);
    return *reinterpret_cast<uint32_t*>(&p);
}
__device__ __forceinline__ uint32_t split_pack_hi(float a, float b,
                                                  float& ra, float& rb) {
    __nv_bfloat16 ha = __float2bfloat16(a), hb = __float2bfloat16(b);
    ra = a - __bfloat162float(ha);
    rb = b - __bfloat162float(hb);
    return pack_bf16(ha, hb);
}
__device__ __forceinline__ float ftanh(float x) {
    float e = __expf(2.0f * x);
    return 1.0f - __fdividef(2.0f, e + 1.0f);
}

// -------- init --------
__global__ void init_kernel(float* __restrict__ loss) {
    int idx = threadIdx.x;
    if (idx < NS) g_maxabs[idx] = 0u;
    if (idx == 0) *loss = 0.0f;
}

// -------- prep W1 -> fp16 [k][n] pitch 136 --------
__global__ void prep_w_kernel(const float* __restrict__ W1) {
    int idx = blockIdx.x * 256 + threadIdx.x;
    int k = idx >> 7, n = idx & 127;
    ((__half*)g_Wh)[k * 136 + n] = __float2half_rn(W1[idx]);
}

// ============ MLP via mma.sync fp16 (A split hi/lo, W single fp16) ============
#define PITCHB  272
#define ATILE   34816
#define SP_OFF  64
#define B1S_OFF 1088
#define W2S_OFF 1600
#define WHI_OFF 2176
#define A_OFF   36992
#define MLP_SMEM 176256

__global__ void __launch_bounds__(384, 1) mlp_mma_kernel(
    const float* __restrict__ f,  const float* __restrict__ b1,
    const float* __restrict__ W2, const float* __restrict__ b2,
    float* __restrict__ scores)
{
    extern __shared__ __align__(1024) char smem[];
    const uint32_t sb = smem_u32(smem);
    const int tid = threadIdx.x;

    if (tid == 0) {
        MBAR_INIT(sb + 16, 128); MBAR_INIT(sb + 24, 128);
        MBAR_INIT(sb + 32, 256); MBAR_INIT(sb + 40, 256);
    }
    for (int i = tid; i < 8704; i += 384)
        ((uint32_t*)(smem + WHI_OFF))[i] = g_Wh[i];
    if (tid < 128) {
        ((float*)(smem + B1S_OFF))[tid] = b1[tid];
        ((float*)(smem + W2S_OFF))[tid] = W2[tid];
    }
    __syncthreads();

    if (tid >= 256) {
        // ---- PRODUCERS (warps 8-11) ----
        const int ptid = tid - 256;
        int lc = 0;
        for (int chunk = blockIdx.x; chunk < NCHUNK; chunk += MLP_GRID, ++lc) {
            const int s = lc & 1;
            if (lc >= 2) MBAR_WAIT(sb + 32 + s * 8, ((lc >> 1) - 1) & 1);
            const float4* src = (const float4*)(f + (size_t)chunk * 16384);
            char* ahi = smem + A_OFF + s * (2 * ATILE);
            char* alo = ahi + ATILE;
#pragma unroll 4
            for (int q = 0; q < 32; q++) {
                int idx = q * 128 + ptid;
                float4 v = __ldg(src + idx);
                int row = idx >> 5, colq = (idx & 31) << 2;
                int off = row * PITCHB + colq * 2;
                __half h0 = __float2half_rn(v.x);
                __half h1 = __float2half_rn(v.y);
                __half h2 = __float2half_rn(v.z);
                __half h3 = __float2half_rn(v.w);
                *(uint2*)(ahi + off) = make_uint2(pack_h16(h0, h1), pack_h16(h2, h3));
                *(uint2*)(alo + off) = make_uint2(
                    pack_h16(__float2half_rn(v.x - __half2float(h0)),
                             __float2half_rn(v.y - __half2float(h1))),
                    pack_h16(__float2half_rn(v.z - __half2float(h2)),
                             __float2half_rn(v.w - __half2float(h3))));
            }
            MBAR_ARRIVE(sb + 16 + s * 8);
        }
    } else {
        // ---- CONSUMERS (warps 0-7) ----
        const int lane = tid & 31, wid = tid >> 5;
        const int warpM = wid >> 1, warpN = wid & 1;
        const int t = lane & 3, g = lane >> 2;
        const int lr = lane & 15, lh = lane >> 4;
        const float b2v = __ldg(b2);
        const float* sh_b1 = (const float*)(smem + B1S_OFF);
        const float* sh_w2 = (const float*)(smem + W2S_OFF);
        float* sp = (float*)(smem + SP_OFF);
        const uint32_t a_off = (uint32_t)((warpM * 32 + lr) * PITCHB + lh * 16);
        const uint32_t b_off = (uint32_t)(lr * PITCHB + (warpN * 64 + lh * 8) * 2);

        int lc = 0;
        for (int chunk = blockIdx.x; chunk < NCHUNK; chunk += MLP_GRID, ++lc) {
            const int s = lc & 1;
            MBAR_WAIT(sb + 16 + s * 8, (lc >> 1) & 1);
            const uint32_t sa_hi = sb + A_OFF + s * (2 * ATILE);
            const uint32_t sa_lo = sa_hi + ATILE;

            float D[2][8][4];
#pragma unroll
            for (int i = 0; i < 2; i++)
#pragma unroll
                for (int j = 0; j < 8; j++)
#pragma unroll
                    for (int q = 0; q < 4; q++) D[i][j][q] = 0.0f;

#pragma unroll
            for (int ks = 0; ks < 8; ks++) {
                uint32_t ah0[4], ah1[4], al0[4], al1[4];
                LDSM_X4(ah0, sa_hi + a_off + ks * 32);
                LDSM_X4(ah1, sa_hi + a_off + 16 * PITCHB + ks * 32);
                LDSM_X4(al0, sa_lo + a_off + ks * 32);
                LDSM_X4(al1, sa_lo + a_off + 16 * PITCHB + ks * 32);
                uint32_t bh[8][2];
#pragma unroll
                for (int p = 0; p < 4; p++) {
                    uint32_t r[4];
                    LDSM_X4T(r, sb + WHI_OFF + b_off + ks * (16 * PITCHB) + p * 32);
                    bh[2*p][0] = r[0]; bh[2*p][1] = r[1];
                    bh[2*p+1][0] = r[2]; bh[2*p+1][1] = r[3];
                }
#pragma unroll
                for (int nf = 0; nf < 8; nf++) {
                    MMA_F16(D[0][nf], ah0, bh[nf]);
                    MMA_F16(D[1][nf], ah1, bh[nf]);
                    MMA_F16(D[0][nf], al0, bh[nf]);
                    MMA_F16(D[1][nf], al1, bh[nf]);
                }
            }
            MBAR_ARRIVE(sb + 32 + s * 8);

            float out_lo[2], out_hi[2];
#pragma unroll
            for (int mf = 0; mf < 2; mf++) {
                float plo = 0.0f, phi = 0.0f;
#pragma unroll
                for (int nf = 0; nf < 8; nf++) {
                    int col = warpN * 64 + nf * 8 + 2 * t;
                    float b1a = sh_b1[col], b1b = sh_b1[col + 1];
                    float w2a = sh_w2[col], w2b = sh_w2[col + 1];
                    plo += ftanh(D[mf][nf][0] + b1a) * w2a + ftanh(D[mf][nf][1] + b1b) * w2b;
                    phi += ftanh(D[mf][nf][2] + b1a) * w2a + ftanh(D[mf][nf][3] + b1b) * w2b;
                }
                plo += __shfl_xor_sync(0xffffffffu, plo, 1);
                plo += __shfl_xor_sync(0xffffffffu, plo, 2);
                phi += __shfl_xor_sync(0xffffffffu, phi, 1);
                phi += __shfl_xor_sync(0xffffffffu, phi, 2);
                out_lo[mf] = plo; out_hi[mf] = phi;
            }
            const int par = lc & 1;
            if (warpN == 0 && t == 0) {
#pragma unroll
                for (int mf = 0; mf < 2; mf++) {
                    int row = warpM * 32 + mf * 16 + g;
                    sp[par * 128 + row]     = out_lo[mf];
                    sp[par * 128 + row + 8] = out_hi[mf];
                }
            }
            asm volatile("bar.sync 1, 256;" ::: "memory");
            if (warpN == 1 && t == 0) {
                float* so = scores + (size_t)chunk * 128;
#pragma unroll
                for (int mf = 0; mf < 2; mf++) {
                    int row = warpM * 32 + mf * 16 + g;
                    so[row]     = out_lo[mf] + sp[par * 128 + row]     + b2v;
                    so[row + 8] = out_hi[mf] + sp[par * 128 + row + 8] + b2v;
                }
            }
        }
    }
}

// -------- cost v2: upper-triangular 32x32 tiles, 4-pair ILP per warp --------
__global__ void __launch_bounds__(256) cost_kernel(const float* __restrict__ f) {
    int n = blockIdx.y;
    int tt = blockIdx.x, bi = 0;          // 36 upper tiles of 8x8 blocks
    while (tt >= 8 - bi) { tt -= 8 - bi; bi++; }
    int bj = bi + tt;
    int w = threadIdx.x >> 5, lane = threadIdx.x & 31;
    const float* fn = f + (size_t)n * (LL * LL * HH);
    float* C = g_C + (size_t)n * (LL * LL);
    float lmax = 0.0f;
    int r0 = bi * 32 + w * 4;
#pragma unroll 1
    for (int c = 0; c < 32; c++) {
        int j = bj * 32 + c;
        float4 x[4], y[4];
#pragma unroll
        for (int p = 0; p < 4; p++) {
            int i = r0 + p;
            x[p] = __ldg((const float4*)(fn + (size_t)(i * LL + j) * HH) + lane);
            y[p] = __ldg((const float4*)(fn + (size_t)(j * LL + i) * HH) + lane);
        }
        float s[4];
#pragma unroll
        for (int p = 0; p < 4; p++)
            s[p] = x[p].x * y[p].x + x[p].y * y[p].y + x[p].z * y[p].z + x[p].w * y[p].w;
#pragma unroll
        for (int o = 16; o > 0; o >>= 1) {
#pragma unroll
            for (int p = 0; p < 4; p++) s[p] += __shfl_xor_sync(0xffffffffu, s[p], o);
        }
        if (lane == 0) {
#pragma unroll
            for (int p = 0; p < 4; p++) {
                int i = r0 + p;
                if (j >= i) {
                    C[i * LL + j] = s[p];
                    C[j * LL + i] = s[p];
                    lmax = fmaxf(lmax, fabsf(s[p]));
                }
            }
        }
    }
    if (lane == 0) atomicMax(&g_maxabs[n], __float_as_uint(lmax));
}

// -------- kexp: K=exp(-LAM*Cn), KM=K*Cn -> split bf16, MMA-A-permuted --------
__global__ void kexp_kernel() {
    int idx = blockIdx.x * blockDim.x + threadIdx.x;
    int n = idx >> 16;
    int r = (idx >> 8) & 255, k = idx & 255;
    float mx = __uint_as_float(g_maxabs[n]);
    float cn = g_C[idx] / (mx + EPSF);
    float kv = expf(-LAMF * cn);
    float km = kv * cn;
    int mt = r >> 4, rl = r & 15, kt = k >> 4, kl = k & 15;
    int T   = ((rl & 7) << 2) + ((kl & 7) >> 1);
    int reg = (rl >> 3) + ((kl >> 3) << 1);
    int pofs = (n << 16) + (((mt << 4) + kt) << 8) + (T << 3) + (reg << 1) + (kl & 1);
    __nv_bfloat16 kh = __float2bfloat16(kv);
    __nv_bfloat16 mh = __float2bfloat16(km);
    g_Kph [pofs] = kh;
    g_Kpl [pofs] = __float2bfloat16(kv - __bfloat162float(kh));
    g_KMph[pofs] = mh;
    g_KMpl[pofs] = __float2bfloat16(km - __bfloat162float(mh));
}

// -------- rT: softmax rows, transposed [n][support][problem] --------
__global__ void softmaxT_kernel(const float* __restrict__ scores) {
    __shared__ float sh[32][257];
    int blk = blockIdx.x;
    int n  = blk >> 3;
    int r0 = (blk & 7) << 5;
    int tid = threadIdx.x;
    int wid = tid >> 5, lane = tid & 31;
    const float* S = scores + ((size_t)n * 256 + r0) * 256;
#pragma unroll
    for (int s4 = 0; s4 < 4; s4++) {
        int rl = wid + 8 * s4;
        const float* row = S + rl * 256;
        float4 v0 = *(const float4*)(row + lane * 4);
        float4 v1 = *(const float4*)(row + 128 + lane * 4);
        float m = fmaxf(fmaxf(fmaxf(v0.x, v0.y), fmaxf(v0.z, v0.w)),
                        fmaxf(fmaxf(v1.x, v1.y), fmaxf(v1.z, v1.w)));
#pragma unroll
        for (int o = 16; o > 0; o >>= 1) m = fmaxf(m, __shfl_xor_sync(0xffffffffu, m, o));
        float e[8];
        e[0] = expf(v0.x - m); e[1] = expf(v0.y - m);
        e[2] = expf(v0.z - m); e[3] = expf(v0.w - m);
        e[4] = expf(v1.x - m); e[5] = expf(v1.y - m);
        e[6] = expf(v1.z - m); e[7] = expf(v1.w - m);
        float sum = e[0]+e[1]+e[2]+e[3]+e[4]+e[5]+e[6]+e[7];
#pragma unroll
        for (int o = 16; o > 0; o >>= 1) sum += __shfl_xor_sync(0xffffffffu, sum, o);
        float inv = 1.0f / sum;
#pragma unroll
        for (int q = 0; q < 4; q++) sh[rl][lane * 4 + q]       = e[q] * inv;
#pragma unroll
        for (int q = 0; q < 4; q++) sh[rl][128 + lane * 4 + q] = e[4 + q] * inv;
    }
    __syncthreads();
    int rloc = tid & 31, cb = tid >> 5;
    float* O = g_rT + (size_t)n * 65536 + r0;
#pragma unroll
    for (int s = 0; s < 32; s++) {
        int col = cb + 8 * s;
        O[(size_t)col * 256 + rloc] = sh[rloc][col];
    }
}

// -------- cT: (head+eps)/rowsum, transposed --------
__global__ void normT_kernel(const float* __restrict__ head) {
    __shared__ float sh[32][257];
    int blk = blockIdx.x;
    int n  = blk >> 3;
    int r0 = (blk & 7) << 5;
    int tid = threadIdx.x;
    int wid = tid >> 5, lane = tid & 31;
    const float* S = head + ((size_t)n * 256 + r0) * 256;
#pragma unroll
    for (int s4 = 0; s4 < 4; s4++) {
        int rl = wid + 8 * s4;
        const float* row = S + rl * 256;
        float4 v0 = *(const float4*)(row + lane * 4);
        float4 v1 = *(const float4*)(row + 128 + lane * 4);
        float e[8] = { v0.x + EPSF, v0.y + EPSF, v0.z + EPSF, v0.w + EPSF,
                       v1.x + EPSF, v1.y + EPSF, v1.z + EPSF, v1.w + EPSF };
        float sum = e[0]+e[1]+e[2]+e[3]+e[4]+e[5]+e[6]+e[7];
#pragma unroll
        for (int o = 16; o > 0; o >>= 1) sum += __shfl_xor_sync(0xffffffffu, sum, o);
        float inv = 1.0f / sum;
#pragma unroll
        for (int q = 0; q < 4; q++) sh[rl][lane * 4 + q]       = e[q] * inv;
#pragma unroll
        for (int q = 0; q < 4; q++) sh[rl][128 + lane * 4 + q] = e[4 + q] * inv;
    }
    __syncthreads();
    int rloc = tid & 31, cb = tid >> 5;
    float* O = g_cT + (size_t)n * 65536 + r0;
#pragma unroll
    for (int s = 0; s < 32; s++) {
        int col = cb + 8 * s;
        O[(size_t)col * 256 + rloc] = sh[rloc][col];
    }
}

// ============ fused Sinkhorn: 20 iters + loss in ONE kernel (bf16 3-term) ============
#define SK_XHI 0
#define SK_XLO 20480
#define SK_UN  40960
#define SK_CN  74752
#define SK_UF  108544
#define SK_RED 142336
#define SK_SMEM 142400

template<bool STORE_U>
__device__ __noinline__ void sink_phase(
    const uint4* __restrict__ Ah, const uint4* __restrict__ Al,
    uint32_t xhi, uint32_t xlo, uint32_t nmb, uint32_t ufb, int w, int lane)
{
    float D[2][4][4];
#pragma unroll
    for (int i = 0; i < 2; i++)
#pragma unroll
        for (int j = 0; j < 4; j++)
#pragma unroll
            for (int q = 0; q < 4; q++) D[i][j][q] = 0.0f;

    const int lr = lane & 15, lh = lane >> 4;
    const uint32_t bhb = xhi + lr * 80 + lh * 16;
    const uint32_t blb = xlo + lr * 80 + lh * 16;
#pragma unroll 4
    for (int kt = 0; kt < 16; kt++) {
        uint4 ah0 = Ah[(size_t)(w * 32 + kt) * 32 + lane];
        uint4 ah1 = Ah[(size_t)(w * 32 + 16 + kt) * 32 + lane];
        uint4 al0 = Al[(size_t)(w * 32 + kt) * 32 + lane];
        uint4 al1 = Al[(size_t)(w * 32 + 16 + kt) * 32 + lane];
        uint32_t bh[4][2], bl[4][2], r[4];
        LDSM_X4T(r, bhb + kt * 1280);      bh[0][0]=r[0]; bh[0][1]=r[1]; bh[1][0]=r[2]; bh[1][1]=r[3];
        LDSM_X4T(r, bhb + kt * 1280 + 32); bh[2][0]=r[0]; bh[2][1]=r[1]; bh[3][0]=r[2]; bh[3][1]=r[3];
        LDSM_X4T(r, blb + kt * 1280);      bl[0][0]=r[0]; bl[0][1]=r[1]; bl[1][0]=r[2]; bl[1][1]=r[3];
        LDSM_X4T(r, blb + kt * 1280 + 32); bl[2][0]=r[0]; bl[2][1]=r[1]; bl[3][0]=r[2]; bl[3][1]=r[3];
#pragma unroll
        for (int nt = 0; nt < 4; nt++) {
            MMA_BF16(D[0][nt], ((uint32_t*)&ah0), bh[nt]);
            MMA_BF16(D[1][nt], ((uint32_t*)&ah1), bh[nt]);
            MMA_BF16(D[0][nt], ((uint32_t*)&al0), bh[nt]);
            MMA_BF16(D[1][nt], ((uint32_t*)&al1), bh[nt]);
            MMA_BF16(D[0][nt], ((uint32_t*)&ah0), bl[nt]);
            MMA_BF16(D[1][nt], ((uint32_t*)&ah1), bl[nt]);
        }
    }
    __syncthreads();
    const int rq = lane >> 2, cq = (lane & 3) * 2;
#pragma unroll
    for (int mt = 0; mt < 2; mt++) {
        int row = w * 32 + mt * 16 + rq;
#pragma unroll
        for (int nt = 0; nt < 4; nt++) {
            int col = nt * 8 + cq;
            float n0 = lds32f(nmb + (row * 33 + col) * 4);
            float n1 = lds32f(nmb + (row * 33 + col + 1) * 4);
            float n2 = lds32f(nmb + ((row + 8) * 33 + col) * 4);
            float n3 = lds32f(nmb + ((row + 8) * 33 + col + 1) * 4);
            float o0 = n0 / (D[mt][nt][0] + EPSF);
            float o1 = n1 / (D[mt][nt][1] + EPSF);
            float o2 = n2 / (D[mt][nt][2] + EPSF);
            float o3 = n3 / (D[mt][nt][3] + EPSF);
            float l0, l1, l2, l3;
            uint32_t h01 = split_pack_hi(o0, o1, l0, l1);
            uint32_t h23 = split_pack_hi(o2, o3, l2, l3);
            sts32(xhi + row * 80 + col * 2, h01);
            sts32(xhi + (row + 8) * 80 + col * 2, h23);
            sts32(xlo + row * 80 + col * 2,
                  pack_bf16(__float2bfloat16(l0), __float2bfloat16(l1)));
            sts32(xlo + (row + 8) * 80 + col * 2,
                  pack_bf16(__float2bfloat16(l2), __float2bfloat16(l3)));
            if (STORE_U) {
                sts32f(ufb + (row * 33 + col) * 4, o0);
                sts32f(ufb + (row * 33 + col + 1) * 4, o1);
                sts32f(ufb + ((row + 8) * 33 + col) * 4, o2);
                sts32f(ufb + ((row + 8) * 33 + col + 1) * 4, o3);
            }
        }
    }
    __syncthreads();
}

__global__ void __launch_bounds__(256, 1) sinkhorn_fused_kernel(float* __restrict__ loss)
{
    extern __shared__ __align__(16) char smem[];
    const uint32_t sb = smem_u32(smem);
    const int tid = threadIdx.x, lane = tid & 31, w = tid >> 5;
    const int n = blockIdx.x >> 3, c0 = (blockIdx.x & 7) * 32;

    const float* rTn = g_rT + (size_t)n * 65536 + c0;
    const float* cTn = g_cT + (size_t)n * 65536 + c0;
    float* UN = (float*)(smem + SK_UN);
    float* CN = (float*)(smem + SK_CN);
    for (int i = tid; i < 8192; i += 256) {
        int r = i >> 5, c = i & 31;
        UN[r * 33 + c] = rTn[(size_t)r * 256 + c];
        CN[r * 33 + c] = cTn[(size_t)r * 256 + c];
    }
    const uint32_t HV = pack_bf16(__float2bfloat16(1.0f / 256.0f),
                                  __float2bfloat16(1.0f / 256.0f));
    for (int i = tid; i < 5120; i += 256) {
        ((uint32_t*)(smem + SK_XHI))[i] = HV;
        ((uint32_t*)(smem + SK_XLO))[i] = 0u;
    }
    __syncthreads();

    const uint4* Kh  = (const uint4*)g_Kph  + (size_t)n * 8192;
    const uint4* Kl  = (const uint4*)g_Kpl  + (size_t)n * 8192;
    const uint4* Mh  = (const uint4*)g_KMph + (size_t)n * 8192;
    const uint4* Ml  = (const uint4*)g_KMpl + (size_t)n * 8192;
    const uint32_t xhi = sb + SK_XHI, xlo = sb + SK_XLO;
    const uint32_t unb = sb + SK_UN, cnb = sb + SK_CN, ufb = sb + SK_UF;

#pragma unroll 1
    for (int it = 0; it < 19; it++) {
        sink_phase<false>(Kh, Kl, xhi, xlo, cnb, ufb, w, lane);
        sink_phase<false>(Kh, Kl, xhi, xlo, unb, ufb, w, lane);
    }
    sink_phase<false>(Kh, Kl, xhi, xlo, cnb, ufb, w, lane);
    sink_phase<true >(Kh, Kl, xhi, xlo, unb, ufb, w, lane);
    sink_phase<false>(Kh, Kl, xhi, xlo, cnb, ufb, w, lane);

    float D[2][4][4];
#pragma unroll
    for (int i = 0; i < 2; i++)
#pragma unroll
        for (int j = 0; j < 4; j++)
#pragma unroll
            for (int q = 0; q < 4; q++) D[i][j][q] = 0.0f;
    {
        const int lr = lane & 15, lh = lane >> 4;
        const uint32_t bhb = xhi + lr * 80 + lh * 16;
        const uint32_t blb = xlo + lr * 80 + lh * 16;
#pragma unroll 4
        for (int kt = 0; kt < 16; kt++) {
            uint4 ah0 = Mh[(size_t)(w * 32 + kt) * 32 + lane];
            uint4 ah1 = Mh[(size_t)(w * 32 + 16 + kt) * 32 + lane];
            uint4 al0 = Ml[(size_t)(w * 32 + kt) * 32 + lane];
            uint4 al1 = Ml[(size_t)(w * 32 + 16 + kt) * 32 + lane];
            uint32_t bh[4][2], bl[4][2], r[4];
            LDSM_X4T(r, bhb + kt * 1280);      bh[0][0]=r[0]; bh[0][1]=r[1]; bh[1][0]=r[2]; bh[1][1]=r[3];
            LDSM_X4T(r, bhb + kt * 1280 + 32); bh[2][0]=r[0]; bh[2][1]=r[1]; bh[3][0]=r[2]; bh[3][1]=r[3];
            LDSM_X4T(r, blb + kt * 1280);      bl[0][0]=r[0]; bl[0][1]=r[1]; bl[1][0]=r[2]; bl[1][1]=r[3];
            LDSM_X4T(r, blb + kt * 1280 + 32); bl[2][0]=r[0]; bl[2][1]=r[1]; bl[3][0]=r[2]; bl[3][1]=r[3];
#pragma unroll
            for (int nt = 0; nt < 4; nt++) {
                MMA_BF16(D[0][nt], ((uint32_t*)&ah0), bh[nt]);
                MMA_BF16(D[1][nt], ((uint32_t*)&ah1), bh[nt]);
                MMA_BF16(D[0][nt], ((uint32_t*)&al0), bh[nt]);
                MMA_BF16(D[1][nt], ((uint32_t*)&al1), bh[nt]);
                MMA_BF16(D[0][nt], ((uint32_t*)&ah0), bl[nt]);
                MMA_BF16(D[1][nt], ((uint32_t*)&ah1), bl[nt]);
            }
        }
    }
    float part = 0.0f;
    {
        const int rq = lane >> 2, cq = (lane & 3) * 2;
#pragma unroll
        for (int mt = 0; mt < 2; mt++) {
            int row = w * 32 + mt * 16 + rq;
#pragma unroll
            for (int nt = 0; nt < 4; nt++) {
                int col = nt * 8 + cq;
                part += lds32f(ufb + (row * 33 + col) * 4)       * D[mt][nt][0];
                part += lds32f(ufb + (row * 33 + col + 1) * 4)   * D[mt][nt][1];
                part += lds32f(ufb + ((row + 8) * 33 + col) * 4) * D[mt][nt][2];
                part += lds32f(ufb + ((row + 8) * 33 + col + 1) * 4) * D[mt][nt][3];
            }
        }
    }
#pragma unroll
    for (int o = 16; o > 0; o >>= 1) part += __shfl_xor_sync(0xffffffffu, part, o);
    float* RED = (float*)(smem + SK_RED);
    if (lane == 0) RED[w] = part;
    __syncthreads();
    if (tid == 0) {
        float t = 0.0f;
#pragma unroll
        for (int i = 0; i < 8; i++) t += RED[i];
        atomicAdd(loss, t);
    }
}

extern "C" void kernel_launch(void* const* d_in, const int* in_sizes, int n_in,
                              void* d_out, int out_size)
{
    const float* f    = (const float*)d_in[0];
    const float* head = (const float*)d_in[1];
    const float* W1   = (const float*)d_in[2];
    const float* b1   = (const float*)d_in[3];
    const float* W2   = (const float*)d_in[4];
    const float* b2   = (const float*)d_in[5];
    float* out    = (float*)d_out;
    float* scores = out;
    float* loss   = out + (out_size - 1);

    cudaFuncSetAttribute(mlp_mma_kernel, cudaFuncAttributeMaxDynamicSharedMemorySize, MLP_SMEM);
    cudaFuncSetAttribute(sinkhorn_fused_kernel, cudaFuncAttributeMaxDynamicSharedMemorySize, SK_SMEM);

    init_kernel<<<1, 256>>>(loss);
    prep_w_kernel<<<64, 256>>>(W1);
    mlp_mma_kernel<<<MLP_GRID, 384, MLP_SMEM>>>(f, b1, W2, b2, scores);
    cost_kernel<<<dim3(36, NS), 256>>>(f);
    kexp_kernel<<<NARC / 256, 256>>>();
    softmaxT_kernel<<<128, 256>>>(scores);
    normT_kernel<<<128, 256>>>(head);
    sinkhorn_fused_kernel<<<128, 256, SK_SMEM>>>(loss);
}

// round 6
// speedup vs baseline: 3.1393x; 1.0399x over previous
#include <cuda_runtime.h>
#include <cuda_bf16.h>
#include <cuda_fp16.h>
#include <math.h>
#include <stdint.h>

#define NS   16
#define LL   256
#define HH   128
#define LAMF 20.0f
#define EPSF 1e-8f
#define NARC (NS * LL * LL)   // 1,048,576
#define NCHUNK 8192
#define MLP_GRID 148

// -------- scratch (allocation-free: device globals) --------
__device__ __align__(16) float g_C [NARC];                 // cost C staging
__device__ __align__(16) float g_rT[NARC];                 // [n][support][problem]
__device__ __align__(16) float g_cT[NARC];
__device__ unsigned int g_maxabs[NS];
__device__ __align__(16) unsigned int g_Wh[8704];          // W1 fp16, padded [k][n] pitch 136
// K/KM split bf16, MMA-A-fragment permuted layout (16B per (tile,lane))
__device__ __align__(16) __nv_bfloat16 g_Kph [NARC];
__device__ __align__(16) __nv_bfloat16 g_Kpl [NARC];
__device__ __align__(16) __nv_bfloat16 g_KMph[NARC];
__device__ __align__(16) __nv_bfloat16 g_KMpl[NARC];

// ================= PTX helpers (baseline sm_103) =================
__device__ __forceinline__ uint32_t smem_u32(const void* p) {
    uint32_t a;
    asm("{ .reg .u64 t; cvta.to.shared.u64 t, %1; cvt.u32.u64 %0, t; }" : "=r"(a) : "l"(p));
    return a;
}
#define MBAR_INIT(addr, cnt) \
    asm volatile("mbarrier.init.shared.b64 [%0], %1;" :: "r"(addr), "r"(cnt) : "memory")
#define MBAR_ARRIVE(addr) \
    asm volatile("mbarrier.arrive.shared.b64 _, [%0];" :: "r"(addr) : "memory")
#define MBAR_WAIT(addr, ph) do { \
    uint32_t _m = (addr); uint32_t _p = (ph); uint32_t _d; \
    asm volatile("{\n\t.reg .pred p;\n\tmbarrier.try_wait.parity.acquire.cta.shared::cta.b64 p, [%1], %2;\n\tselp.b32 %0, 1, 0, p;\n\t}" \
        : "=r"(_d) : "r"(_m), "r"(_p) : "memory"); \
    if (!_d) { \
        asm volatile("{\n\t.reg .pred P1;\n\tWL_%=:\n\tmbarrier.try_wait.parity.acquire.cta.shared::cta.b64 P1, [%0], %1, 0x989680;\n\t@P1 bra.uni WD_%=;\n\tbra.uni WL_%=;\n\tWD_%=:\n\t}" \
            :: "r"(_m), "r"(_p) : "memory"); \
    } } while (0)
#define LDSM_X4(r, addr) \
    asm volatile("ldmatrix.sync.aligned.m8n8.x4.shared.b16 {%0,%1,%2,%3}, [%4];" \
        : "=r"((r)[0]), "=r"((r)[1]), "=r"((r)[2]), "=r"((r)[3]) : "r"(addr))
#define LDSM_X4T(r, addr) \
    asm volatile("ldmatrix.sync.aligned.m8n8.x4.trans.shared.b16 {%0,%1,%2,%3}, [%4];" \
        : "=r"((r)[0]), "=r"((r)[1]), "=r"((r)[2]), "=r"((r)[3]) : "r"(addr))
#define MMA_BF16(d, a, b) \
    asm volatile("mma.sync.aligned.m16n8k16.row.col.f32.bf16.bf16.f32 " \
        "{%0,%1,%2,%3}, {%4,%5,%6,%7}, {%8,%9}, {%0,%1,%2,%3};" \
        : "+f"((d)[0]), "+f"((d)[1]), "+f"((d)[2]), "+f"((d)[3]) \
        : "r"((a)[0]), "r"((a)[1]), "r"((a)[2]), "r"((a)[3]), "r"((b)[0]), "r"((b)[1]))
#define MMA_F16(d, a, b) \
    asm volatile("mma.sync.aligned.m16n8k16.row.col.f32.f16.f16.f32 " \
        "{%0,%1,%2,%3}, {%4,%5,%6,%7}, {%8,%9}, {%0,%1,%2,%3};" \
        : "+f"((d)[0]), "+f"((d)[1]), "+f"((d)[2]), "+f"((d)[3]) \
        : "r"((a)[0]), "r"((a)[1]), "r"((a)[2]), "r"((a)[3]), "r"((b)[0]), "r"((b)[1]))
__device__ __forceinline__ void sts32(uint32_t addr, uint32_t v) {
    asm volatile("st.shared.b32 [%0], %1;" :: "r"(addr), "r"(v) : "memory");
}
__device__ __forceinline__ float lds32f(uint32_t addr) {
    float v; asm volatile("ld.shared.f32 %0, [%1];" : "=f"(v) : "r"(addr)); return v;
}
__device__ __forceinline__ void sts32f(uint32_t addr, float v) {
    asm volatile("st.shared.f32 [%0], %1;" :: "r"(addr), "f"(v) : "memory");
}
__device__ __forceinline__ uint32_t pack_bf16(__nv_bfloat16 a, __nv_bfloat16 b) {
    __nv_bfloat162 p = __halves2bfloat162(a, b);
    return *reinterpret_cast<uint32_t*>(&p);
}
__device__ __forceinline__ uint32_t pack_h16(__half a, __half b) {
    __half2 p = __halves2half2(a, b);
    return *reinterpret_cast<uint32_t*>(&p);
}
__device__ __forceinline__ uint32_t split_pack_hi(float a, float b,
                                                  float& ra, float& rb) {
    __nv_bfloat16 ha = __float2bfloat16(a), hb = __float2bfloat16(b);
    ra = a - __bfloat162float(ha);
    rb = b - __bfloat162float(hb);
    return pack_bf16(ha, hb);
}
__device__ __forceinline__ float ftanh(float x) {
    float r; asm("tanh.approx.f32 %0, %1;" : "=f"(r) : "f"(x)); return r;
}

// -------- init --------
__global__ void init_kernel(float* __restrict__ loss) {
    int idx = threadIdx.x;
    if (idx < NS) g_maxabs[idx] = 0u;
    if (idx == 0) *loss = 0.0f;
}

// -------- prep W1 -> fp16 [k][n] pitch 136 --------
__global__ void prep_w_kernel(const float* __restrict__ W1) {
    int idx = blockIdx.x * 256 + threadIdx.x;
    int k = idx >> 7, n = idx & 127;
    ((__half*)g_Wh)[k * 136 + n] = __float2half_rn(W1[idx]);
}

// ============ MLP via mma.sync fp16 (single-term A and W) ============
#define PITCHB  272
#define ATILE   34816
#define SP_OFF  64
#define B1S_OFF 1088
#define W2S_OFF 1600
#define WHI_OFF 2176
#define A_OFF   36992
#define MLP_SMEM 106624

__global__ void __launch_bounds__(384, 1) mlp_mma_kernel(
    const float* __restrict__ f,  const float* __restrict__ b1,
    const float* __restrict__ W2, const float* __restrict__ b2,
    float* __restrict__ scores)
{
    extern __shared__ __align__(1024) char smem[];
    const uint32_t sb = smem_u32(smem);
    const int tid = threadIdx.x;

    if (tid == 0) {
        MBAR_INIT(sb + 16, 128); MBAR_INIT(sb + 24, 128);
        MBAR_INIT(sb + 32, 256); MBAR_INIT(sb + 40, 256);
    }
    for (int i = tid; i < 8704; i += 384)
        ((uint32_t*)(smem + WHI_OFF))[i] = g_Wh[i];
    if (tid < 128) {
        ((float*)(smem + B1S_OFF))[tid] = b1[tid];
        ((float*)(smem + W2S_OFF))[tid] = W2[tid];
    }
    __syncthreads();

    if (tid >= 256) {
        // ---- PRODUCERS (warps 8-11) ----
        const int ptid = tid - 256;
        int lc = 0;
        for (int chunk = blockIdx.x; chunk < NCHUNK; chunk += MLP_GRID, ++lc) {
            const int s = lc & 1;
            if (lc >= 2) MBAR_WAIT(sb + 32 + s * 8, ((lc >> 1) - 1) & 1);
            const float4* src = (const float4*)(f + (size_t)chunk * 16384);
            char* ahi = smem + A_OFF + s * ATILE;
#pragma unroll 4
            for (int q = 0; q < 32; q++) {
                int idx = q * 128 + ptid;
                float4 v = __ldg(src + idx);
                int row = idx >> 5, colq = (idx & 31) << 2;
                int off = row * PITCHB + colq * 2;
                *(uint2*)(ahi + off) = make_uint2(
                    pack_h16(__float2half_rn(v.x), __float2half_rn(v.y)),
                    pack_h16(__float2half_rn(v.z), __float2half_rn(v.w)));
            }
            MBAR_ARRIVE(sb + 16 + s * 8);
        }
    } else {
        // ---- CONSUMERS (warps 0-7) ----
        const int lane = tid & 31, wid = tid >> 5;
        const int warpM = wid >> 1, warpN = wid & 1;
        const int t = lane & 3, g = lane >> 2;
        const int lr = lane & 15, lh = lane >> 4;
        const float b2v = __ldg(b2);
        const float* sh_b1 = (const float*)(smem + B1S_OFF);
        const float* sh_w2 = (const float*)(smem + W2S_OFF);
        float* sp = (float*)(smem + SP_OFF);
        const uint32_t a_off = (uint32_t)((warpM * 32 + lr) * PITCHB + lh * 16);
        const uint32_t b_off = (uint32_t)(lr * PITCHB + (warpN * 64 + lh * 8) * 2);

        int lc = 0;
        for (int chunk = blockIdx.x; chunk < NCHUNK; chunk += MLP_GRID, ++lc) {
            const int s = lc & 1;
            MBAR_WAIT(sb + 16 + s * 8, (lc >> 1) & 1);
            const uint32_t sa_hi = sb + A_OFF + s * ATILE;

            float D[2][8][4];
#pragma unroll
            for (int i = 0; i < 2; i++)
#pragma unroll
                for (int j = 0; j < 8; j++)
#pragma unroll
                    for (int q = 0; q < 4; q++) D[i][j][q] = 0.0f;

#pragma unroll
            for (int ks = 0; ks < 8; ks++) {
                uint32_t ah0[4], ah1[4];
                LDSM_X4(ah0, sa_hi + a_off + ks * 32);
                LDSM_X4(ah1, sa_hi + a_off + 16 * PITCHB + ks * 32);
                uint32_t bh[8][2];
#pragma unroll
                for (int p = 0; p < 4; p++) {
                    uint32_t r[4];
                    LDSM_X4T(r, sb + WHI_OFF + b_off + ks * (16 * PITCHB) + p * 32);
                    bh[2*p][0] = r[0]; bh[2*p][1] = r[1];
                    bh[2*p+1][0] = r[2]; bh[2*p+1][1] = r[3];
                }
#pragma unroll
                for (int nf = 0; nf < 8; nf++) {
                    MMA_F16(D[0][nf], ah0, bh[nf]);
                    MMA_F16(D[1][nf], ah1, bh[nf]);
                }
            }
            MBAR_ARRIVE(sb + 32 + s * 8);

            float out_lo[2], out_hi[2];
#pragma unroll
            for (int mf = 0; mf < 2; mf++) {
                float plo = 0.0f, phi = 0.0f;
#pragma unroll
                for (int nf = 0; nf < 8; nf++) {
                    int col = warpN * 64 + nf * 8 + 2 * t;
                    float b1a = sh_b1[col], b1b = sh_b1[col + 1];
                    float w2a = sh_w2[col], w2b = sh_w2[col + 1];
                    plo += ftanh(D[mf][nf][0] + b1a) * w2a + ftanh(D[mf][nf][1] + b1b) * w2b;
                    phi += ftanh(D[mf][nf][2] + b1a) * w2a + ftanh(D[mf][nf][3] + b1b) * w2b;
                }
                plo += __shfl_xor_sync(0xffffffffu, plo, 1);
                plo += __shfl_xor_sync(0xffffffffu, plo, 2);
                phi += __shfl_xor_sync(0xffffffffu, phi, 1);
                phi += __shfl_xor_sync(0xffffffffu, phi, 2);
                out_lo[mf] = plo; out_hi[mf] = phi;
            }
            const int par = lc & 1;
            if (warpN == 0 && t == 0) {
#pragma unroll
                for (int mf = 0; mf < 2; mf++) {
                    int row = warpM * 32 + mf * 16 + g;
                    sp[par * 128 + row]     = out_lo[mf];
                    sp[par * 128 + row + 8] = out_hi[mf];
                }
            }
            asm volatile("bar.sync 1, 256;" ::: "memory");
            if (warpN == 1 && t == 0) {
                float* so = scores + (size_t)chunk * 128;
#pragma unroll
                for (int mf = 0; mf < 2; mf++) {
                    int row = warpM * 32 + mf * 16 + g;
                    so[row]     = out_lo[mf] + sp[par * 128 + row]     + b2v;
                    so[row + 8] = out_hi[mf] + sp[par * 128 + row + 8] + b2v;
                }
            }
        }
    }
}

// -------- cost: upper-triangular 32x32 tiles, diag loads predicated --------
__global__ void __launch_bounds__(256) cost_kernel(const float* __restrict__ f) {
    int n = blockIdx.y;
    int tt = blockIdx.x, bi = 0;          // 36 upper tiles of 8x8 blocks
    while (tt >= 8 - bi) { tt -= 8 - bi; bi++; }
    int bj = bi + tt;
    int w = threadIdx.x >> 5, lane = threadIdx.x & 31;
    const float* fn = f + (size_t)n * (LL * LL * HH);
    float* C = g_C + (size_t)n * (LL * LL);
    float lmax = 0.0f;
    int r0 = bi * 32 + w * 4;
#pragma unroll 1
    for (int c = 0; c < 32; c++) {
        int j = bj * 32 + c;
        float4 x[4], y[4];
#pragma unroll
        for (int p = 0; p < 4; p++) {
            int i = r0 + p;
            if (j >= i) {
                x[p] = __ldg((const float4*)(fn + (size_t)(i * LL + j) * HH) + lane);
                y[p] = __ldg((const float4*)(fn + (size_t)(j * LL + i) * HH) + lane);
            } else {
                x[p] = make_float4(0.f, 0.f, 0.f, 0.f);
                y[p] = x[p];
            }
        }
        float s[4];
#pragma unroll
        for (int p = 0; p < 4; p++)
            s[p] = x[p].x * y[p].x + x[p].y * y[p].y + x[p].z * y[p].z + x[p].w * y[p].w;
#pragma unroll
        for (int o = 16; o > 0; o >>= 1) {
#pragma unroll
            for (int p = 0; p < 4; p++) s[p] += __shfl_xor_sync(0xffffffffu, s[p], o);
        }
        if (lane == 0) {
#pragma unroll
            for (int p = 0; p < 4; p++) {
                int i = r0 + p;
                if (j >= i) {
                    C[i * LL + j] = s[p];
                    C[j * LL + i] = s[p];
                    lmax = fmaxf(lmax, fabsf(s[p]));
                }
            }
        }
    }
    if (lane == 0) atomicMax(&g_maxabs[n], __float_as_uint(lmax));
}

// -------- kexp: K=exp(-LAM*Cn), KM=K*Cn -> split bf16, MMA-A-permuted --------
__global__ void kexp_kernel() {
    int idx = blockIdx.x * blockDim.x + threadIdx.x;
    int n = idx >> 16;
    int r = (idx >> 8) & 255, k = idx & 255;
    float mx = __uint_as_float(g_maxabs[n]);
    float cn = g_C[idx] / (mx + EPSF);
    float kv = expf(-LAMF * cn);
    float km = kv * cn;
    int mt = r >> 4, rl = r & 15, kt = k >> 4, kl = k & 15;
    int T   = ((rl & 7) << 2) + ((kl & 7) >> 1);
    int reg = (rl >> 3) + ((kl >> 3) << 1);
    int pofs = (n << 16) + (((mt << 4) + kt) << 8) + (T << 3) + (reg << 1) + (kl & 1);
    __nv_bfloat16 kh = __float2bfloat16(kv);
    __nv_bfloat16 mh = __float2bfloat16(km);
    g_Kph [pofs] = kh;
    g_Kpl [pofs] = __float2bfloat16(kv - __bfloat162float(kh));
    g_KMph[pofs] = mh;
    g_KMpl[pofs] = __float2bfloat16(km - __bfloat162float(mh));
}

// -------- rT: softmax rows, transposed [n][support][problem] --------
__global__ void softmaxT_kernel(const float* __restrict__ scores) {
    __shared__ float sh[32][257];
    int blk = blockIdx.x;
    int n  = blk >> 3;
    int r0 = (blk & 7) << 5;
    int tid = threadIdx.x;
    int wid = tid >> 5, lane = tid & 31;
    const float* S = scores + ((size_t)n * 256 + r0) * 256;
#pragma unroll
    for (int s4 = 0; s4 < 4; s4++) {
        int rl = wid + 8 * s4;
        const float* row = S + rl * 256;
        float4 v0 = *(const float4*)(row + lane * 4);
        float4 v1 = *(const float4*)(row + 128 + lane * 4);
        float m = fmaxf(fmaxf(fmaxf(v0.x, v0.y), fmaxf(v0.z, v0.w)),
                        fmaxf(fmaxf(v1.x, v1.y), fmaxf(v1.z, v1.w)));
#pragma unroll
        for (int o = 16; o > 0; o >>= 1) m = fmaxf(m, __shfl_xor_sync(0xffffffffu, m, o));
        float e[8];
        e[0] = expf(v0.x - m); e[1] = expf(v0.y - m);
        e[2] = expf(v0.z - m); e[3] = expf(v0.w - m);
        e[4] = expf(v1.x - m); e[5] = expf(v1.y - m);
        e[6] = expf(v1.z - m); e[7] = expf(v1.w - m);
        float sum = e[0]+e[1]+e[2]+e[3]+e[4]+e[5]+e[6]+e[7];
#pragma unroll
        for (int o = 16; o > 0; o >>= 1) sum += __shfl_xor_sync(0xffffffffu, sum, o);
        float inv = 1.0f / sum;
#pragma unroll
        for (int q = 0; q < 4; q++) sh[rl][lane * 4 + q]       = e[q] * inv;
#pragma unroll
        for (int q = 0; q < 4; q++) sh[rl][128 + lane * 4 + q] = e[4 + q] * inv;
    }
    __syncthreads();
    int rloc = tid & 31, cb = tid >> 5;
    float* O = g_rT + (size_t)n * 65536 + r0;
#pragma unroll
    for (int s = 0; s < 32; s++) {
        int col = cb + 8 * s;
        O[(size_t)col * 256 + rloc] = sh[rloc][col];
    }
}

// -------- cT: (head+eps)/rowsum, transposed --------
__global__ void normT_kernel(const float* __restrict__ head) {
    __shared__ float sh[32][257];
    int blk = blockIdx.x;
    int n  = blk >> 3;
    int r0 = (blk & 7) << 5;
    int tid = threadIdx.x;
    int wid = tid >> 5, lane = tid & 31;
    const float* S = head + ((size_t)n * 256 + r0) * 256;
#pragma unroll
    for (int s4 = 0; s4 < 4; s4++) {
        int rl = wid + 8 * s4;
        const float* row = S + rl * 256;
        float4 v0 = *(const float4*)(row + lane * 4);
        float4 v1 = *(const float4*)(row + 128 + lane * 4);
        float e[8] = { v0.x + EPSF, v0.y + EPSF, v0.z + EPSF, v0.w + EPSF,
                       v1.x + EPSF, v1.y + EPSF, v1.z + EPSF, v1.w + EPSF };
        float sum = e[0]+e[1]+e[2]+e[3]+e[4]+e[5]+e[6]+e[7];
#pragma unroll
        for (int o = 16; o > 0; o >>= 1) sum += __shfl_xor_sync(0xffffffffu, sum, o);
        float inv = 1.0f / sum;
#pragma unroll
        for (int q = 0; q < 4; q++) sh[rl][lane * 4 + q]       = e[q] * inv;
#pragma unroll
        for (int q = 0; q < 4; q++) sh[rl][128 + lane * 4 + q] = e[4 + q] * inv;
    }
    __syncthreads();
    int rloc = tid & 31, cb = tid >> 5;
    float* O = g_cT + (size_t)n * 65536 + r0;
#pragma unroll
    for (int s = 0; s < 32; s++) {
        int col = cb + 8 * s;
        O[(size_t)col * 256 + rloc] = sh[rloc][col];
    }
}

// ============ fused Sinkhorn: 20 iters + loss in ONE kernel (bf16 3-term) ============
#define SK_XHI 0
#define SK_XLO 20480
#define SK_UN  40960
#define SK_CN  74752
#define SK_UF  108544
#define SK_RED 142336
#define SK_SMEM 142400

template<bool STORE_U>
__device__ __noinline__ void sink_phase(
    const uint4* __restrict__ Ah, const uint4* __restrict__ Al,
    uint32_t xhi, uint32_t xlo, uint32_t nmb, uint32_t ufb, int w, int lane)
{
    float D[2][4][4];
#pragma unroll
    for (int i = 0; i < 2; i++)
#pragma unroll
        for (int j = 0; j < 4; j++)
#pragma unroll
            for (int q = 0; q < 4; q++) D[i][j][q] = 0.0f;

    const int lr = lane & 15, lh = lane >> 4;
    const uint32_t bhb = xhi + lr * 80 + lh * 16;
    const uint32_t blb = xlo + lr * 80 + lh * 16;
#pragma unroll 4
    for (int kt = 0; kt < 16; kt++) {
        uint4 ah0 = Ah[(size_t)(w * 32 + kt) * 32 + lane];
        uint4 ah1 = Ah[(size_t)(w * 32 + 16 + kt) * 32 + lane];
        uint4 al0 = Al[(size_t)(w * 32 + kt) * 32 + lane];
        uint4 al1 = Al[(size_t)(w * 32 + 16 + kt) * 32 + lane];
        uint32_t bh[4][2], bl[4][2], r[4];
        LDSM_X4T(r, bhb + kt * 1280);      bh[0][0]=r[0]; bh[0][1]=r[1]; bh[1][0]=r[2]; bh[1][1]=r[3];
        LDSM_X4T(r, bhb + kt * 1280 + 32); bh[2][0]=r[0]; bh[2][1]=r[1]; bh[3][0]=r[2]; bh[3][1]=r[3];
        LDSM_X4T(r, blb + kt * 1280);      bl[0][0]=r[0]; bl[0][1]=r[1]; bl[1][0]=r[2]; bl[1][1]=r[3];
        LDSM_X4T(r, blb + kt * 1280 + 32); bl[2][0]=r[0]; bl[2][1]=r[1]; bl[3][0]=r[2]; bl[3][1]=r[3];
#pragma unroll
        for (int nt = 0; nt < 4; nt++) {
            MMA_BF16(D[0][nt], ((uint32_t*)&ah0), bh[nt]);
            MMA_BF16(D[1][nt], ((uint32_t*)&ah1), bh[nt]);
            MMA_BF16(D[0][nt], ((uint32_t*)&al0), bh[nt]);
            MMA_BF16(D[1][nt], ((uint32_t*)&al1), bh[nt]);
            MMA_BF16(D[0][nt], ((uint32_t*)&ah0), bl[nt]);
            MMA_BF16(D[1][nt], ((uint32_t*)&ah1), bl[nt]);
        }
    }
    __syncthreads();
    const int rq = lane >> 2, cq = (lane & 3) * 2;
#pragma unroll
    for (int mt = 0; mt < 2; mt++) {
        int row = w * 32 + mt * 16 + rq;
#pragma unroll
        for (int nt = 0; nt < 4; nt++) {
            int col = nt * 8 + cq;
            float n0 = lds32f(nmb + (row * 33 + col) * 4);
            float n1 = lds32f(nmb + (row * 33 + col + 1) * 4);
            float n2 = lds32f(nmb + ((row + 8) * 33 + col) * 4);
            float n3 = lds32f(nmb + ((row + 8) * 33 + col + 1) * 4);
            float o0 = n0 / (D[mt][nt][0] + EPSF);
            float o1 = n1 / (D[mt][nt][1] + EPSF);
            float o2 = n2 / (D[mt][nt][2] + EPSF);
            float o3 = n3 / (D[mt][nt][3] + EPSF);
            float l0, l1, l2, l3;
            uint32_t h01 = split_pack_hi(o0, o1, l0, l1);
            uint32_t h23 = split_pack_hi(o2, o3, l2, l3);
            sts32(xhi + row * 80 + col * 2, h01);
            sts32(xhi + (row + 8) * 80 + col * 2, h23);
            sts32(xlo + row * 80 + col * 2,
                  pack_bf16(__float2bfloat16(l0), __float2bfloat16(l1)));
            sts32(xlo + (row + 8) * 80 + col * 2,
                  pack_bf16(__float2bfloat16(l2), __float2bfloat16(l3)));
            if (STORE_U) {
                sts32f(ufb + (row * 33 + col) * 4, o0);
                sts32f(ufb + (row * 33 + col + 1) * 4, o1);
                sts32f(ufb + ((row + 8) * 33 + col) * 4, o2);
                sts32f(ufb + ((row + 8) * 33 + col + 1) * 4, o3);
            }
        }
    }
    __syncthreads();
}

__global__ void __launch_bounds__(256, 1) sinkhorn_fused_kernel(float* __restrict__ loss)
{
    extern __shared__ __align__(16) char smem[];
    const uint32_t sb = smem_u32(smem);
    const int tid = threadIdx.x, lane = tid & 31, w = tid >> 5;
    const int n = blockIdx.x >> 3, c0 = (blockIdx.x & 7) * 32;

    const float* rTn = g_rT + (size_t)n * 65536 + c0;
    const float* cTn = g_cT + (size_t)n * 65536 + c0;
    float* UN = (float*)(smem + SK_UN);
    float* CN = (float*)(smem + SK_CN);
    for (int i = tid; i < 8192; i += 256) {
        int r = i >> 5, c = i & 31;
        UN[r * 33 + c] = rTn[(size_t)r * 256 + c];
        CN[r * 33 + c] = cTn[(size_t)r * 256 + c];
    }
    const uint32_t HV = pack_bf16(__float2bfloat16(1.0f / 256.0f),
                                  __float2bfloat16(1.0f / 256.0f));
    for (int i = tid; i < 5120; i += 256) {
        ((uint32_t*)(smem + SK_XHI))[i] = HV;
        ((uint32_t*)(smem + SK_XLO))[i] = 0u;
    }
    __syncthreads();

    const uint4* Kh  = (const uint4*)g_Kph  + (size_t)n * 8192;
    const uint4* Kl  = (const uint4*)g_Kpl  + (size_t)n * 8192;
    const uint4* Mh  = (const uint4*)g_KMph + (size_t)n * 8192;
    const uint4* Ml  = (const uint4*)g_KMpl + (size_t)n * 8192;
    const uint32_t xhi = sb + SK_XHI, xlo = sb + SK_XLO;
    const uint32_t unb = sb + SK_UN, cnb = sb + SK_CN, ufb = sb + SK_UF;

#pragma unroll 1
    for (int it = 0; it < 19; it++) {
        sink_phase<false>(Kh, Kl, xhi, xlo, cnb, ufb, w, lane);
        sink_phase<false>(Kh, Kl, xhi, xlo, unb, ufb, w, lane);
    }
    sink_phase<false>(Kh, Kl, xhi, xlo, cnb, ufb, w, lane);
    sink_phase<true >(Kh, Kl, xhi, xlo, unb, ufb, w, lane);
    sink_phase<false>(Kh, Kl, xhi, xlo, cnb, ufb, w, lane);

    float D[2][4][4];
#pragma unroll
    for (int i = 0; i < 2; i++)
#pragma unroll
        for (int j = 0; j < 4; j++)
#pragma unroll
            for (int q = 0; q < 4; q++) D[i][j][q] = 0.0f;
    {
        const int lr = lane & 15, lh = lane >> 4;
        const uint32_t bhb = xhi + lr * 80 + lh * 16;
        const uint32_t blb = xlo + lr * 80 + lh * 16;
#pragma unroll 4
        for (int kt = 0; kt < 16; kt++) {
            uint4 ah0 = Mh[(size_t)(w * 32 + kt) * 32 + lane];
            uint4 ah1 = Mh[(size_t)(w * 32 + 16 + kt) * 32 + lane];
            uint4 al0 = Ml[(size_t)(w * 32 + kt) * 32 + lane];
            uint4 al1 = Ml[(size_t)(w * 32 + 16 + kt) * 32 + lane];
            uint32_t bh[4][2], bl[4][2], r[4];
            LDSM_X4T(r, bhb + kt * 1280);      bh[0][0]=r[0]; bh[0][1]=r[1]; bh[1][0]=r[2]; bh[1][1]=r[3];
            LDSM_X4T(r, bhb + kt * 1280 + 32); bh[2][0]=r[0]; bh[2][1]=r[1]; bh[3][0]=r[2]; bh[3][1]=r[3];
            LDSM_X4T(r, blb + kt * 1280);      bl[0][0]=r[0]; bl[0][1]=r[1]; bl[1][0]=r[2]; bl[1][1]=r[3];
            LDSM_X4T(r, blb + kt * 1280 + 32); bl[2][0]=r[0]; bl[2][1]=r[1]; bl[3][0]=r[2]; bl[3][1]=r[3];
#pragma unroll
            for (int nt = 0; nt < 4; nt++) {
                MMA_BF16(D[0][nt], ((uint32_t*)&ah0), bh[nt]);
                MMA_BF16(D[1][nt], ((uint32_t*)&ah1), bh[nt]);
                MMA_BF16(D[0][nt], ((uint32_t*)&al0), bh[nt]);
                MMA_BF16(D[1][nt], ((uint32_t*)&al1), bh[nt]);
                MMA_BF16(D[0][nt], ((uint32_t*)&ah0), bl[nt]);
                MMA_BF16(D[1][nt], ((uint32_t*)&ah1), bl[nt]);
            }
        }
    }
    float part = 0.0f;
    {
        const int rq = lane >> 2, cq = (lane & 3) * 2;
#pragma unroll
        for (int mt = 0; mt < 2; mt++) {
            int row = w * 32 + mt * 16 + rq;
#pragma unroll
            for (int nt = 0; nt < 4; nt++) {
                int col = nt * 8 + cq;
                part += lds32f(ufb + (row * 33 + col) * 4)       * D[mt][nt][0];
                part += lds32f(ufb + (row * 33 + col + 1) * 4)   * D[mt][nt][1];
                part += lds32f(ufb + ((row + 8) * 33 + col) * 4) * D[mt][nt][2];
                part += lds32f(ufb + ((row + 8) * 33 + col + 1) * 4) * D[mt][nt][3];
            }
        }
    }
#pragma unroll
    for (int o = 16; o > 0; o >>= 1) part += __shfl_xor_sync(0xffffffffu, part, o);
    float* RED = (float*)(smem + SK_RED);
    if (lane == 0) RED[w] = part;
    __syncthreads();
    if (tid == 0) {
        float t = 0.0f;
#pragma unroll
        for (int i = 0; i < 8; i++) t += RED[i];
        atomicAdd(loss, t);
    }
}

extern "C" void kernel_launch(void* const* d_in, const int* in_sizes, int n_in,
                              void* d_out, int out_size)
{
    const float* f    = (const float*)d_in[0];
    const float* head = (const float*)d_in[1];
    const float* W1   = (const float*)d_in[2];
    const float* b1   = (const float*)d_in[3];
    const float* W2   = (const float*)d_in[4];
    const float* b2   = (const float*)d_in[5];
    float* out    = (float*)d_out;
    float* scores = out;
    float* loss   = out + (out_size - 1);

    cudaFuncSetAttribute(mlp_mma_kernel, cudaFuncAttributeMaxDynamicSharedMemorySize, MLP_SMEM);
    cudaFuncSetAttribute(sinkhorn_fused_kernel, cudaFuncAttributeMaxDynamicSharedMemorySize, SK_SMEM);

    init_kernel<<<1, 256>>>(loss);
    prep_w_kernel<<<64, 256>>>(W1);
    mlp_mma_kernel<<<MLP_GRID, 384, MLP_SMEM>>>(f, b1, W2, b2, scores);
    cost_kernel<<<dim3(36, NS), 256>>>(f);
    kexp_kernel<<<NARC / 256, 256>>>();
    softmaxT_kernel<<<128, 256>>>(scores);
    normT_kernel<<<128, 256>>>(head);
    sinkhorn_fused_kernel<<<128, 256, SK_SMEM>>>(loss);
}

// round 7
// speedup vs baseline: 3.2582x; 1.0379x over previous
#include <cuda_runtime.h>
#include <cuda_bf16.h>
#include <cuda_fp16.h>
#include <math.h>
#include <stdint.h>

#define NS   16
#define LL   256
#define HH   128
#define LAMF 20.0f
#define EPSF 1e-8f
#define NARC (NS * LL * LL)   // 1,048,576
#define NCHUNK 8192
#define MLP_GRID 148

// -------- scratch (allocation-free: device globals) --------
__device__ __align__(16) float g_C [NARC];                 // cost C staging
__device__ unsigned int g_maxabs[NS];
// K/KM split bf16, MMA-A-fragment permuted layout (16B per (tile,lane))
__device__ __align__(16) __nv_bfloat16 g_Kph [NARC];
__device__ __align__(16) __nv_bfloat16 g_Kpl [NARC];
__device__ __align__(16) __nv_bfloat16 g_KMph[NARC];
__device__ __align__(16) __nv_bfloat16 g_KMpl[NARC];

// ================= PTX helpers (baseline sm_103) =================
__device__ __forceinline__ uint32_t smem_u32(const void* p) {
    uint32_t a;
    asm("{ .reg .u64 t; cvta.to.shared.u64 t, %1; cvt.u32.u64 %0, t; }" : "=r"(a) : "l"(p));
    return a;
}
#define MBAR_INIT(addr, cnt) \
    asm volatile("mbarrier.init.shared.b64 [%0], %1;" :: "r"(addr), "r"(cnt) : "memory")
#define MBAR_ARRIVE(addr) \
    asm volatile("mbarrier.arrive.shared.b64 _, [%0];" :: "r"(addr) : "memory")
#define MBAR_WAIT(addr, ph) do { \
    uint32_t _m = (addr); uint32_t _p = (ph); uint32_t _d; \
    asm volatile("{\n\t.reg .pred p;\n\tmbarrier.try_wait.parity.acquire.cta.shared::cta.b64 p, [%1], %2;\n\tselp.b32 %0, 1, 0, p;\n\t}" \
        : "=r"(_d) : "r"(_m), "r"(_p) : "memory"); \
    if (!_d) { \
        asm volatile("{\n\t.reg .pred P1;\n\tWL_%=:\n\tmbarrier.try_wait.parity.acquire.cta.shared::cta.b64 P1, [%0], %1, 0x989680;\n\t@P1 bra.uni WD_%=;\n\tbra.uni WL_%=;\n\tWD_%=:\n\t}" \
            :: "r"(_m), "r"(_p) : "memory"); \
    } } while (0)
#define LDSM_X4(r, addr) \
    asm volatile("ldmatrix.sync.aligned.m8n8.x4.shared.b16 {%0,%1,%2,%3}, [%4];" \
        : "=r"((r)[0]), "=r"((r)[1]), "=r"((r)[2]), "=r"((r)[3]) : "r"(addr))
#define LDSM_X4T(r, addr) \
    asm volatile("ldmatrix.sync.aligned.m8n8.x4.trans.shared.b16 {%0,%1,%2,%3}, [%4];" \
        : "=r"((r)[0]), "=r"((r)[1]), "=r"((r)[2]), "=r"((r)[3]) : "r"(addr))
#define MMA_BF16(d, a, b) \
    asm volatile("mma.sync.aligned.m16n8k16.row.col.f32.bf16.bf16.f32 " \
        "{%0,%1,%2,%3}, {%4,%5,%6,%7}, {%8,%9}, {%0,%1,%2,%3};" \
        : "+f"((d)[0]), "+f"((d)[1]), "+f"((d)[2]), "+f"((d)[3]) \
        : "r"((a)[0]), "r"((a)[1]), "r"((a)[2]), "r"((a)[3]), "r"((b)[0]), "r"((b)[1]))
#define MMA_F16(d, a, b) \
    asm volatile("mma.sync.aligned.m16n8k16.row.col.f32.f16.f16.f32 " \
        "{%0,%1,%2,%3}, {%4,%5,%6,%7}, {%8,%9}, {%0,%1,%2,%3};" \
        : "+f"((d)[0]), "+f"((d)[1]), "+f"((d)[2]), "+f"((d)[3]) \
        : "r"((a)[0]), "r"((a)[1]), "r"((a)[2]), "r"((a)[3]), "r"((b)[0]), "r"((b)[1]))
__device__ __forceinline__ void sts32(uint32_t addr, uint32_t v) {
    asm volatile("st.shared.b32 [%0], %1;" :: "r"(addr), "r"(v) : "memory");
}
__device__ __forceinline__ float lds32f(uint32_t addr) {
    float v; asm volatile("ld.shared.f32 %0, [%1];" : "=f"(v) : "r"(addr)); return v;
}
__device__ __forceinline__ void sts32f(uint32_t addr, float v) {
    asm volatile("st.shared.f32 [%0], %1;" :: "r"(addr), "f"(v) : "memory");
}
// packed cvt: low half <- lo, high half <- hi
#define CVT2BF(dst, hi, lo) \
    asm("cvt.rn.bf16x2.f32 %0, %1, %2;" : "=r"(dst) : "f"(hi), "f"(lo))
__device__ __forceinline__ uint32_t pack_bf16(__nv_bfloat16 a, __nv_bfloat16 b) {
    __nv_bfloat162 p = __halves2bfloat162(a, b);
    return *reinterpret_cast<uint32_t*>(&p);
}
__device__ __forceinline__ uint32_t pack_h16(__half a, __half b) {
    __half2 p = __halves2half2(a, b);
    return *reinterpret_cast<uint32_t*>(&p);
}
__device__ __forceinline__ float ftanh(float x) {
    float r; asm("tanh.approx.f32 %0, %1;" : "=f"(r) : "f"(x)); return r;
}

// -------- init --------
__global__ void init_kernel(float* __restrict__ loss) {
    int idx = threadIdx.x;
    if (idx < NS) g_maxabs[idx] = 0u;
    if (idx == 0) *loss = 0.0f;
}

// ============ COMBO: MLP (mma.sync fp16) + cost fused into producers ============
#define PITCHB  272
#define ATILE   34816
#define SP_OFF  64
#define B1S_OFF 1088
#define W2S_OFF 1600
#define WHI_OFF 2176
#define A_OFF   36992
#define MLP_SMEM 106624

__global__ void __launch_bounds__(384, 1) combo_kernel(
    const float* __restrict__ f,  const float* __restrict__ W1,
    const float* __restrict__ b1, const float* __restrict__ W2,
    const float* __restrict__ b2, float* __restrict__ scores)
{
    extern __shared__ __align__(1024) char smem[];
    const uint32_t sb = smem_u32(smem);
    const int tid = threadIdx.x;

    if (tid == 0) {
        MBAR_INIT(sb + 16, 128); MBAR_INIT(sb + 24, 128);
        MBAR_INIT(sb + 32, 256); MBAR_INIT(sb + 40, 256);
    }
    // W1 fp32 -> fp16 smem [k][n] pitch 136 (inline prep)
    for (int i = tid; i < 16384; i += 384) {
        int k = i >> 7, nn = i & 127;
        ((__half*)(smem + WHI_OFF))[k * 136 + nn] = __float2half_rn(W1[i]);
    }
    if (tid < 128) {
        ((float*)(smem + B1S_OFF))[tid] = b1[tid];
        ((float*)(smem + W2S_OFF))[tid] = W2[tid];
    }
    __syncthreads();

    if (tid >= 256) {
        // ---- PRODUCERS (warps 8-11): MLP A-tile staging + cost dots ----
        const int ptid = tid - 256;
        const int pw = ptid >> 5, lane = ptid & 31;
        int lc = 0;
        for (int chunk = blockIdx.x; chunk < NCHUNK; chunk += MLP_GRID, ++lc) {
            const int s = lc & 1;
            if (lc >= 2) MBAR_WAIT(sb + 32 + s * 8, ((lc >> 1) - 1) & 1);
            const float4* src = (const float4*)(f + (size_t)chunk * 16384);
            char* ahi = smem + A_OFF + s * ATILE;
#pragma unroll 4
            for (int q = 0; q < 32; q++) {
                int idx = q * 128 + ptid;
                float4 v = __ldg(src + idx);
                int row = idx >> 5, colq = (idx & 31) << 2;
                int off = row * PITCHB + colq * 2;
                *(uint2*)(ahi + off) = make_uint2(
                    pack_h16(__float2half_rn(v.x), __float2half_rn(v.y)),
                    pack_h16(__float2half_rn(v.z), __float2half_rn(v.w)));
            }
            MBAR_ARRIVE(sb + 16 + s * 8);   // consumers may start MMA

            // ---- cost: this warp owns arcs pw*32 .. pw*32+31 of the chunk ----
            const int n = chunk >> 9;
            float* C = g_C;
            float lmax = 0.0f;
            float4 xa[2][4], ya[2][4];
            // prologue batch 0
#pragma unroll
            for (int p = 0; p < 4; p++) {
                int arc = chunk * 128 + pw * 32 + p;
                int ij = arc & 65535;
                int i2 = ij >> 8, j2 = ij & 255;
                xa[0][p] = __ldg((const float4*)(f + (size_t)arc * 128) + lane);
                ya[0][p] = __ldg((const float4*)(f + (((size_t)n << 16) + (j2 << 8) + i2) * 128) + lane);
            }
#pragma unroll
            for (int b = 0; b < 8; b++) {
                int cur = b & 1;
                if (b < 7) {
#pragma unroll
                    for (int p = 0; p < 4; p++) {
                        int arc = chunk * 128 + pw * 32 + (b + 1) * 4 + p;
                        int ij = arc & 65535;
                        int i2 = ij >> 8, j2 = ij & 255;
                        xa[cur ^ 1][p] = __ldg((const float4*)(f + (size_t)arc * 128) + lane);
                        ya[cur ^ 1][p] = __ldg((const float4*)(f + (((size_t)n << 16) + (j2 << 8) + i2) * 128) + lane);
                    }
                }
                float sdot[4];
#pragma unroll
                for (int p = 0; p < 4; p++)
                    sdot[p] = xa[cur][p].x * ya[cur][p].x + xa[cur][p].y * ya[cur][p].y
                            + xa[cur][p].z * ya[cur][p].z + xa[cur][p].w * ya[cur][p].w;
#pragma unroll
                for (int o = 16; o > 0; o >>= 1) {
#pragma unroll
                    for (int p = 0; p < 4; p++)
                        sdot[p] += __shfl_xor_sync(0xffffffffu, sdot[p], o);
                }
#pragma unroll
                for (int p = 0; p < 4; p++) lmax = fmaxf(lmax, fabsf(sdot[p]));
                if (lane < 4)   // lane p writes arc p (coalesced-ish, 4 consecutive)
                    C[chunk * 128 + pw * 32 + b * 4 + lane] = sdot[lane];
            }
            if (lane == 0) atomicMax(&g_maxabs[n], __float_as_uint(lmax));
        }
    } else {
        // ---- CONSUMERS (warps 0-7) ----
        const int lane = tid & 31, wid = tid >> 5;
        const int warpM = wid >> 1, warpN = wid & 1;
        const int t = lane & 3, g = lane >> 2;
        const int lr = lane & 15, lh = lane >> 4;
        const float b2v = __ldg(b2);
        const float* sh_b1 = (const float*)(smem + B1S_OFF);
        const float* sh_w2 = (const float*)(smem + W2S_OFF);
        float* sp = (float*)(smem + SP_OFF);
        const uint32_t a_off = (uint32_t)((warpM * 32 + lr) * PITCHB + lh * 16);
        const uint32_t b_off = (uint32_t)(lr * PITCHB + (warpN * 64 + lh * 8) * 2);

        int lc = 0;
        for (int chunk = blockIdx.x; chunk < NCHUNK; chunk += MLP_GRID, ++lc) {
            const int s = lc & 1;
            MBAR_WAIT(sb + 16 + s * 8, (lc >> 1) & 1);
            const uint32_t sa_hi = sb + A_OFF + s * ATILE;

            float D[2][8][4];
#pragma unroll
            for (int i = 0; i < 2; i++)
#pragma unroll
                for (int j = 0; j < 8; j++)
#pragma unroll
                    for (int q = 0; q < 4; q++) D[i][j][q] = 0.0f;

#pragma unroll
            for (int ks = 0; ks < 8; ks++) {
                uint32_t ah0[4], ah1[4];
                LDSM_X4(ah0, sa_hi + a_off + ks * 32);
                LDSM_X4(ah1, sa_hi + a_off + 16 * PITCHB + ks * 32);
                uint32_t bh[8][2];
#pragma unroll
                for (int p = 0; p < 4; p++) {
                    uint32_t r[4];
                    LDSM_X4T(r, sb + WHI_OFF + b_off + ks * (16 * PITCHB) + p * 32);
                    bh[2*p][0] = r[0]; bh[2*p][1] = r[1];
                    bh[2*p+1][0] = r[2]; bh[2*p+1][1] = r[3];
                }
#pragma unroll
                for (int nf = 0; nf < 8; nf++) {
                    MMA_F16(D[0][nf], ah0, bh[nf]);
                    MMA_F16(D[1][nf], ah1, bh[nf]);
                }
            }
            MBAR_ARRIVE(sb + 32 + s * 8);

            float out_lo[2], out_hi[2];
#pragma unroll
            for (int mf = 0; mf < 2; mf++) {
                float plo = 0.0f, phi = 0.0f;
#pragma unroll
                for (int nf = 0; nf < 8; nf++) {
                    int col = warpN * 64 + nf * 8 + 2 * t;
                    float b1a = sh_b1[col], b1b = sh_b1[col + 1];
                    float w2a = sh_w2[col], w2b = sh_w2[col + 1];
                    plo += ftanh(D[mf][nf][0] + b1a) * w2a + ftanh(D[mf][nf][1] + b1b) * w2b;
                    phi += ftanh(D[mf][nf][2] + b1a) * w2a + ftanh(D[mf][nf][3] + b1b) * w2b;
                }
                plo += __shfl_xor_sync(0xffffffffu, plo, 1);
                plo += __shfl_xor_sync(0xffffffffu, plo, 2);
                phi += __shfl_xor_sync(0xffffffffu, phi, 1);
                phi += __shfl_xor_sync(0xffffffffu, phi, 2);
                out_lo[mf] = plo; out_hi[mf] = phi;
            }
            const int par = lc & 1;
            if (warpN == 0 && t == 0) {
#pragma unroll
                for (int mf = 0; mf < 2; mf++) {
                    int row = warpM * 32 + mf * 16 + g;
                    sp[par * 128 + row]     = out_lo[mf];
                    sp[par * 128 + row + 8] = out_hi[mf];
                }
            }
            asm volatile("bar.sync 1, 256;" ::: "memory");
            if (warpN == 1 && t == 0) {
                float* so = scores + (size_t)chunk * 128;
#pragma unroll
                for (int mf = 0; mf < 2; mf++) {
                    int row = warpM * 32 + mf * 16 + g;
                    so[row]     = out_lo[mf] + sp[par * 128 + row]     + b2v;
                    so[row + 8] = out_hi[mf] + sp[par * 128 + row + 8] + b2v;
                }
            }
        }
    }
}

// -------- kexp: K=exp(-LAM*Cn), KM=K*Cn -> split bf16, MMA-A-permuted --------
__global__ void kexp_kernel() {
    int idx = blockIdx.x * blockDim.x + threadIdx.x;
    int n = idx >> 16;
    int r = (idx >> 8) & 255, k = idx & 255;
    float mx = __uint_as_float(g_maxabs[n]);
    float cn = g_C[idx] / (mx + EPSF);
    float kv = __expf(-LAMF * cn);
    float km = kv * cn;
    int mt = r >> 4, rl = r & 15, kt = k >> 4, kl = k & 15;
    int T   = ((rl & 7) << 2) + ((kl & 7) >> 1);
    int reg = (rl >> 3) + ((kl >> 3) << 1);
    int pofs = (n << 16) + (((mt << 4) + kt) << 8) + (T << 3) + (reg << 1) + (kl & 1);
    __nv_bfloat16 kh = __float2bfloat16(kv);
    __nv_bfloat16 mh = __float2bfloat16(km);
    g_Kph [pofs] = kh;
    g_Kpl [pofs] = __float2bfloat16(kv - __bfloat162float(kh));
    g_KMph[pofs] = mh;
    g_KMpl[pofs] = __float2bfloat16(km - __bfloat162float(mh));
}

// ============ fused Sinkhorn: softmax/norm prologue + 20 iters + loss ============
#define SK_XHI 0
#define SK_XLO 20480
#define SK_UN  40960
#define SK_CN  74752
#define SK_UF  108544
#define SK_RED 142336
#define SK_SMEM 142400

template<bool STORE_U>
__device__ __noinline__ void sink_phase(
    const uint4* __restrict__ Ah, const uint4* __restrict__ Al,
    uint32_t xhi, uint32_t xlo, uint32_t nmb, uint32_t ufb, int w, int lane)
{
    float D[2][4][4];
#pragma unroll
    for (int i = 0; i < 2; i++)
#pragma unroll
        for (int j = 0; j < 4; j++)
#pragma unroll
            for (int q = 0; q < 4; q++) D[i][j][q] = 0.0f;

    const int lr = lane & 15, lh = lane >> 4;
    const uint32_t bhb = xhi + lr * 80 + lh * 16;
    const uint32_t blb = xlo + lr * 80 + lh * 16;
#pragma unroll 4
    for (int kt = 0; kt < 16; kt++) {
        uint4 ah0 = Ah[(size_t)(w * 32 + kt) * 32 + lane];
        uint4 ah1 = Ah[(size_t)(w * 32 + 16 + kt) * 32 + lane];
        uint4 al0 = Al[(size_t)(w * 32 + kt) * 32 + lane];
        uint4 al1 = Al[(size_t)(w * 32 + 16 + kt) * 32 + lane];
        uint32_t bh[4][2], bl[4][2], r[4];
        LDSM_X4T(r, bhb + kt * 1280);      bh[0][0]=r[0]; bh[0][1]=r[1]; bh[1][0]=r[2]; bh[1][1]=r[3];
        LDSM_X4T(r, bhb + kt * 1280 + 32); bh[2][0]=r[0]; bh[2][1]=r[1]; bh[3][0]=r[2]; bh[3][1]=r[3];
        LDSM_X4T(r, blb + kt * 1280);      bl[0][0]=r[0]; bl[0][1]=r[1]; bl[1][0]=r[2]; bl[1][1]=r[3];
        LDSM_X4T(r, blb + kt * 1280 + 32); bl[2][0]=r[0]; bl[2][1]=r[1]; bl[3][0]=r[2]; bl[3][1]=r[3];
#pragma unroll
        for (int nt = 0; nt < 4; nt++) {
            MMA_BF16(D[0][nt], ((uint32_t*)&ah0), bh[nt]);
            MMA_BF16(D[1][nt], ((uint32_t*)&ah1), bh[nt]);
            MMA_BF16(D[0][nt], ((uint32_t*)&al0), bh[nt]);
            MMA_BF16(D[1][nt], ((uint32_t*)&al1), bh[nt]);
            MMA_BF16(D[0][nt], ((uint32_t*)&ah0), bl[nt]);
            MMA_BF16(D[1][nt], ((uint32_t*)&ah1), bl[nt]);
        }
    }
    __syncthreads();
    const int rq = lane >> 2, cq = (lane & 3) * 2;
#pragma unroll
    for (int mt = 0; mt < 2; mt++) {
        int row = w * 32 + mt * 16 + rq;
#pragma unroll
        for (int nt = 0; nt < 4; nt++) {
            int col = nt * 8 + cq;
            float n0 = lds32f(nmb + (row * 33 + col) * 4);
            float n1 = lds32f(nmb + (row * 33 + col + 1) * 4);
            float n2 = lds32f(nmb + ((row + 8) * 33 + col) * 4);
            float n3 = lds32f(nmb + ((row + 8) * 33 + col + 1) * 4);
            float o0 = __fdividef(n0, D[mt][nt][0] + EPSF);
            float o1 = __fdividef(n1, D[mt][nt][1] + EPSF);
            float o2 = __fdividef(n2, D[mt][nt][2] + EPSF);
            float o3 = __fdividef(n3, D[mt][nt][3] + EPSF);
            uint32_t h01, h23, l01, l23;
            CVT2BF(h01, o1, o0);
            CVT2BF(h23, o3, o2);
            float l0 = o0 - __uint_as_float(h01 << 16);
            float l1 = o1 - __uint_as_float(h01 & 0xffff0000u);
            float l2 = o2 - __uint_as_float(h23 << 16);
            float l3 = o3 - __uint_as_float(h23 & 0xffff0000u);
            CVT2BF(l01, l1, l0);
            CVT2BF(l23, l3, l2);
            sts32(xhi + row * 80 + col * 2, h01);
            sts32(xhi + (row + 8) * 80 + col * 2, h23);
            sts32(xlo + row * 80 + col * 2, l01);
            sts32(xlo + (row + 8) * 80 + col * 2, l23);
            if (STORE_U) {
                sts32f(ufb + (row * 33 + col) * 4, o0);
                sts32f(ufb + (row * 33 + col + 1) * 4, o1);
                sts32f(ufb + ((row + 8) * 33 + col) * 4, o2);
                sts32f(ufb + ((row + 8) * 33 + col + 1) * 4, o3);
            }
        }
    }
    __syncthreads();
}

__global__ void __launch_bounds__(256, 1) sinkhorn_fused_kernel(
    const float* __restrict__ scores, const float* __restrict__ head,
    float* __restrict__ loss)
{
    extern __shared__ __align__(16) char smem[];
    const uint32_t sb = smem_u32(smem);
    const int tid = threadIdx.x, lane = tid & 31, w = tid >> 5;
    const int n = blockIdx.x >> 3, c0 = (blockIdx.x & 7) * 32;

    float* UN = (float*)(smem + SK_UN);
    float* CN = (float*)(smem + SK_CN);
    // ---- prologue: softmax(scores rows) and normalized head rows, transposed ----
#pragma unroll
    for (int q = 0; q < 4; q++) {
        int p = w * 4 + q;
        const float* row = scores + ((size_t)(n * 256 + c0 + p)) * 256;
        float4 v0 = *(const float4*)(row + lane * 4);
        float4 v1 = *(const float4*)(row + 128 + lane * 4);
        float m = fmaxf(fmaxf(fmaxf(v0.x, v0.y), fmaxf(v0.z, v0.w)),
                        fmaxf(fmaxf(v1.x, v1.y), fmaxf(v1.z, v1.w)));
#pragma unroll
        for (int o = 16; o > 0; o >>= 1) m = fmaxf(m, __shfl_xor_sync(0xffffffffu, m, o));
        float e[8];
        e[0] = __expf(v0.x - m); e[1] = __expf(v0.y - m);
        e[2] = __expf(v0.z - m); e[3] = __expf(v0.w - m);
        e[4] = __expf(v1.x - m); e[5] = __expf(v1.y - m);
        e[6] = __expf(v1.z - m); e[7] = __expf(v1.w - m);
        float sum = e[0]+e[1]+e[2]+e[3]+e[4]+e[5]+e[6]+e[7];
#pragma unroll
        for (int o = 16; o > 0; o >>= 1) sum += __shfl_xor_sync(0xffffffffu, sum, o);
        float inv = __fdividef(1.0f, sum);
#pragma unroll
        for (int k = 0; k < 4; k++) UN[(lane * 4 + k) * 33 + p]       = e[k] * inv;
#pragma unroll
        for (int k = 0; k < 4; k++) UN[(128 + lane * 4 + k) * 33 + p] = e[4 + k] * inv;

        const float* hrow = head + ((size_t)(n * 256 + c0 + p)) * 256;
        float4 h0 = *(const float4*)(hrow + lane * 4);
        float4 h1 = *(const float4*)(hrow + 128 + lane * 4);
        float he[8] = { h0.x + EPSF, h0.y + EPSF, h0.z + EPSF, h0.w + EPSF,
                        h1.x + EPSF, h1.y + EPSF, h1.z + EPSF, h1.w + EPSF };
        float hsum = he[0]+he[1]+he[2]+he[3]+he[4]+he[5]+he[6]+he[7];
#pragma unroll
        for (int o = 16; o > 0; o >>= 1) hsum += __shfl_xor_sync(0xffffffffu, hsum, o);
        float hinv = __fdividef(1.0f, hsum);
#pragma unroll
        for (int k = 0; k < 4; k++) CN[(lane * 4 + k) * 33 + p]       = he[k] * hinv;
#pragma unroll
        for (int k = 0; k < 4; k++) CN[(128 + lane * 4 + k) * 33 + p] = he[4 + k] * hinv;
    }
    const uint32_t HV = pack_bf16(__float2bfloat16(1.0f / 256.0f),
                                  __float2bfloat16(1.0f / 256.0f));
    for (int i = tid; i < 5120; i += 256) {
        ((uint32_t*)(smem + SK_XHI))[i] = HV;
        ((uint32_t*)(smem + SK_XLO))[i] = 0u;
    }
    __syncthreads();

    const uint4* Kh  = (const uint4*)g_Kph  + (size_t)n * 8192;
    const uint4* Kl  = (const uint4*)g_Kpl  + (size_t)n * 8192;
    const uint4* Mh  = (const uint4*)g_KMph + (size_t)n * 8192;
    const uint4* Ml  = (const uint4*)g_KMpl + (size_t)n * 8192;
    const uint32_t xhi = sb + SK_XHI, xlo = sb + SK_XLO;
    const uint32_t unb = sb + SK_UN, cnb = sb + SK_CN, ufb = sb + SK_UF;

#pragma unroll 1
    for (int it = 0; it < 19; it++) {
        sink_phase<false>(Kh, Kl, xhi, xlo, cnb, ufb, w, lane);
        sink_phase<false>(Kh, Kl, xhi, xlo, unb, ufb, w, lane);
    }
    sink_phase<false>(Kh, Kl, xhi, xlo, cnb, ufb, w, lane);
    sink_phase<true >(Kh, Kl, xhi, xlo, unb, ufb, w, lane);
    sink_phase<false>(Kh, Kl, xhi, xlo, cnb, ufb, w, lane);

    float D[2][4][4];
#pragma unroll
    for (int i = 0; i < 2; i++)
#pragma unroll
        for (int j = 0; j < 4; j++)
#pragma unroll
            for (int q = 0; q < 4; q++) D[i][j][q] = 0.0f;
    {
        const int lr = lane & 15, lh = lane >> 4;
        const uint32_t bhb = xhi + lr * 80 + lh * 16;
        const uint32_t blb = xlo + lr * 80 + lh * 16;
#pragma unroll 4
        for (int kt = 0; kt < 16; kt++) {
            uint4 ah0 = Mh[(size_t)(w * 32 + kt) * 32 + lane];
            uint4 ah1 = Mh[(size_t)(w * 32 + 16 + kt) * 32 + lane];
            uint4 al0 = Ml[(size_t)(w * 32 + kt) * 32 + lane];
            uint4 al1 = Ml[(size_t)(w * 32 + 16 + kt) * 32 + lane];
            uint32_t bh[4][2], bl[4][2], r[4];
            LDSM_X4T(r, bhb + kt * 1280);      bh[0][0]=r[0]; bh[0][1]=r[1]; bh[1][0]=r[2]; bh[1][1]=r[3];
            LDSM_X4T(r, bhb + kt * 1280 + 32); bh[2][0]=r[0]; bh[2][1]=r[1]; bh[3][0]=r[2]; bh[3][1]=r[3];
            LDSM_X4T(r, blb + kt * 1280);      bl[0][0]=r[0]; bl[0][1]=r[1]; bl[1][0]=r[2]; bl[1][1]=r[3];
            LDSM_X4T(r, blb + kt * 1280 + 32); bl[2][0]=r[0]; bl[2][1]=r[1]; bl[3][0]=r[2]; bl[3][1]=r[3];
#pragma unroll
            for (int nt = 0; nt < 4; nt++) {
                MMA_BF16(D[0][nt], ((uint32_t*)&ah0), bh[nt]);
                MMA_BF16(D[1][nt], ((uint32_t*)&ah1), bh[nt]);
                MMA_BF16(D[0][nt], ((uint32_t*)&al0), bh[nt]);
                MMA_BF16(D[1][nt], ((uint32_t*)&al1), bh[nt]);
                MMA_BF16(D[0][nt], ((uint32_t*)&ah0), bl[nt]);
                MMA_BF16(D[1][nt], ((uint32_t*)&ah1), bl[nt]);
            }
        }
    }
    float part = 0.0f;
    {
        const int rq = lane >> 2, cq = (lane & 3) * 2;
#pragma unroll
        for (int mt = 0; mt < 2; mt++) {
            int row = w * 32 + mt * 16 + rq;
#pragma unroll
            for (int nt = 0; nt < 4; nt++) {
                int col = nt * 8 + cq;
                part += lds32f(ufb + (row * 33 + col) * 4)       * D[mt][nt][0];
                part += lds32f(ufb + (row * 33 + col + 1) * 4)   * D[mt][nt][1];
                part += lds32f(ufb + ((row + 8) * 33 + col) * 4) * D[mt][nt][2];
                part += lds32f(ufb + ((row + 8) * 33 + col + 1) * 4) * D[mt][nt][3];
            }
        }
    }
#pragma unroll
    for (int o = 16; o > 0; o >>= 1) part += __shfl_xor_sync(0xffffffffu, part, o);
    float* RED = (float*)(smem + SK_RED);
    if (lane == 0) RED[w] = part;
    __syncthreads();
    if (tid == 0) {
        float t = 0.0f;
#pragma unroll
        for (int i = 0; i < 8; i++) t += RED[i];
        atomicAdd(loss, t);
    }
}

extern "C" void kernel_launch(void* const* d_in, const int* in_sizes, int n_in,
                              void* d_out, int out_size)
{
    const float* f    = (const float*)d_in[0];
    const float* head = (const float*)d_in[1];
    const float* W1   = (const float*)d_in[2];
    const float* b1   = (const float*)d_in[3];
    const float* W2   = (const float*)d_in[4];
    const float* b2   = (const float*)d_in[5];
    float* out    = (float*)d_out;
    float* scores = out;
    float* loss   = out + (out_size - 1);

    cudaFuncSetAttribute(combo_kernel, cudaFuncAttributeMaxDynamicSharedMemorySize, MLP_SMEM);
    cudaFuncSetAttribute(sinkhorn_fused_kernel, cudaFuncAttributeMaxDynamicSharedMemorySize, SK_SMEM);

    init_kernel<<<1, 256>>>(loss);
    combo_kernel<<<MLP_GRID, 384, MLP_SMEM>>>(f, W1, b1, W2, b2, scores);
    kexp_kernel<<<NARC / 256, 256>>>();
    sinkhorn_fused_kernel<<<128, 256, SK_SMEM>>>(scores, head, loss);
}

// round 8
// speedup vs baseline: 3.5333x; 1.0844x over previous
#include <cuda_runtime.h>
#include <cuda_bf16.h>
#include <cuda_fp16.h>
#include <math.h>
#include <stdint.h>

#define NS   16
#define LL   256
#define HH   128
#define LAMF 20.0f
#define EPSF 1e-8f
#define NARC (NS * LL * LL)
#define NCHUNK 8192
#define MLP_GRID 148
#define COST_GRID (NS * 36)

// -------- scratch --------
__device__ __align__(16) float g_C [NARC];
__device__ unsigned int g_maxabs[NS];
__device__ __align__(16) __nv_bfloat16 g_Kph [NARC];
__device__ __align__(16) __nv_bfloat16 g_Kpl [NARC];
__device__ __align__(16) __nv_bfloat16 g_KMph[NARC];
__device__ __align__(16) __nv_bfloat16 g_KMpl[NARC];

// ================= PTX helpers (baseline sm_103) =================
__device__ __forceinline__ uint32_t smem_u32(const void* p) {
    uint32_t a;
    asm("{ .reg .u64 t; cvta.to.shared.u64 t, %1; cvt.u32.u64 %0, t; }" : "=r"(a) : "l"(p));
    return a;
}
#define MBAR_INIT(addr, cnt) \
    asm volatile("mbarrier.init.shared.b64 [%0], %1;" :: "r"(addr), "r"(cnt) : "memory")
#define MBAR_ARRIVE(addr) \
    asm volatile("mbarrier.arrive.shared.b64 _, [%0];" :: "r"(addr) : "memory")
#define MBAR_WAIT(addr, ph) do { \
    uint32_t _m = (addr); uint32_t _p = (ph); uint32_t _d; \
    asm volatile("{\n\t.reg .pred p;\n\tmbarrier.try_wait.parity.acquire.cta.shared::cta.b64 p, [%1], %2;\n\tselp.b32 %0, 1, 0, p;\n\t}" \
        : "=r"(_d) : "r"(_m), "r"(_p) : "memory"); \
    if (!_d) { \
        asm volatile("{\n\t.reg .pred P1;\n\tWL_%=:\n\tmbarrier.try_wait.parity.acquire.cta.shared::cta.b64 P1, [%0], %1, 0x989680;\n\t@P1 bra.uni WD_%=;\n\tbra.uni WL_%=;\n\tWD_%=:\n\t}" \
            :: "r"(_m), "r"(_p) : "memory"); \
    } } while (0)
#define LDSM_X4(r, addr) \
    asm volatile("ldmatrix.sync.aligned.m8n8.x4.shared.b16 {%0,%1,%2,%3}, [%4];" \
        : "=r"((r)[0]), "=r"((r)[1]), "=r"((r)[2]), "=r"((r)[3]) : "r"(addr))
#define LDSM_X4T(r, addr) \
    asm volatile("ldmatrix.sync.aligned.m8n8.x4.trans.shared.b16 {%0,%1,%2,%3}, [%4];" \
        : "=r"((r)[0]), "=r"((r)[1]), "=r"((r)[2]), "=r"((r)[3]) : "r"(addr))
#define MMA_BF16(d, a, b) \
    asm volatile("mma.sync.aligned.m16n8k16.row.col.f32.bf16.bf16.f32 " \
        "{%0,%1,%2,%3}, {%4,%5,%6,%7}, {%8,%9}, {%0,%1,%2,%3};" \
        : "+f"((d)[0]), "+f"((d)[1]), "+f"((d)[2]), "+f"((d)[3]) \
        : "r"((a)[0]), "r"((a)[1]), "r"((a)[2]), "r"((a)[3]), "r"((b)[0]), "r"((b)[1]))
#define MMA_F16(d, a, b) \
    asm volatile("mma.sync.aligned.m16n8k16.row.col.f32.f16.f16.f32 " \
        "{%0,%1,%2,%3}, {%4,%5,%6,%7}, {%8,%9}, {%0,%1,%2,%3};" \
        : "+f"((d)[0]), "+f"((d)[1]), "+f"((d)[2]), "+f"((d)[3]) \
        : "r"((a)[0]), "r"((a)[1]), "r"((a)[2]), "r"((a)[3]), "r"((b)[0]), "r"((b)[1]))
__device__ __forceinline__ void sts32(uint32_t addr, uint32_t v) {
    asm volatile("st.shared.b32 [%0], %1;" :: "r"(addr), "r"(v) : "memory");
}
__device__ __forceinline__ float lds32f(uint32_t addr) {
    float v; asm volatile("ld.shared.f32 %0, [%1];" : "=f"(v) : "r"(addr)); return v;
}
__device__ __forceinline__ void sts32f(uint32_t addr, float v) {
    asm volatile("st.shared.f32 [%0], %1;" :: "r"(addr), "f"(v) : "memory");
}
#define CVT2BF(dst, hi, lo) \
    asm("cvt.rn.bf16x2.f32 %0, %1, %2;" : "=r"(dst) : "f"(hi), "f"(lo))
__device__ __forceinline__ uint32_t pack_bf16(__nv_bfloat16 a, __nv_bfloat16 b) {
    __nv_bfloat162 p = __halves2bfloat162(a, b);
    return *reinterpret_cast<uint32_t*>(&p);
}
__device__ __forceinline__ uint32_t pack_h16(__half a, __half b) {
    __half2 p = __halves2half2(a, b);
    return *reinterpret_cast<uint32_t*>(&p);
}
__device__ __forceinline__ float ftanh(float x) {
    float r; asm("tanh.approx.f32 %0, %1;" : "=f"(r) : "f"(x)); return r;
}

// -------- init --------
__global__ void init_kernel(float* __restrict__ loss) {
    int idx = threadIdx.x;
    if (idx < NS) g_maxabs[idx] = 0u;
    if (idx == 0) *loss = 0.0f;
}

// ============ MERGED: MLP CTAs (0..147) + cost CTAs (148..723) ============
#define PITCHB  272
#define ATILE   34816
#define SP_OFF  64
#define B1S_OFF 1088
#define W2S_OFF 1600
#define WHI_OFF 2176
#define A_OFF   36992
#define MLP_SMEM 106624

__global__ void __launch_bounds__(384, 1) merged_kernel(
    const float* __restrict__ f,  const float* __restrict__ W1,
    const float* __restrict__ b1, const float* __restrict__ W2,
    const float* __restrict__ b2, float* __restrict__ scores)
{
    extern __shared__ __align__(1024) char smem[];
    const int tid = threadIdx.x;

    if (blockIdx.x >= MLP_GRID) {
        // ================= COST ROLE (576 CTAs, 12 warps) =================
        const int cb = blockIdx.x - MLP_GRID;
        const int n = cb / 36;
        int tt = cb % 36, bi = 0;
        while (tt >= 8 - bi) { tt -= 8 - bi; bi++; }
        const int bj = bi + tt;
        const int w = tid >> 5, lane = tid & 31;
        const float* fn = f + (size_t)n * (LL * LL * HH);
        float* C = g_C + (size_t)n * (LL * LL);
        float lmax = 0.0f;
#pragma unroll 1
        for (int a0 = w * 4; a0 < 1024; a0 += 48) {
            int r = a0 >> 5, cc = a0 & 31;
            int i = bi * 32 + r;
            float4 x[4], y[4];
#pragma unroll
            for (int p = 0; p < 4; p++) {
                int j = bj * 32 + cc + p;
                if (j >= i) {
                    x[p] = __ldg((const float4*)(fn + (size_t)(i * LL + j) * HH) + lane);
                    y[p] = __ldg((const float4*)(fn + (size_t)(j * LL + i) * HH) + lane);
                } else {
                    x[p] = make_float4(0.f, 0.f, 0.f, 0.f);
                    y[p] = x[p];
                }
            }
            float s[4];
#pragma unroll
            for (int p = 0; p < 4; p++)
                s[p] = x[p].x * y[p].x + x[p].y * y[p].y + x[p].z * y[p].z + x[p].w * y[p].w;
#pragma unroll
            for (int o = 16; o > 0; o >>= 1) {
#pragma unroll
                for (int p = 0; p < 4; p++) s[p] += __shfl_xor_sync(0xffffffffu, s[p], o);
            }
            if (lane == 0) {
#pragma unroll
                for (int p = 0; p < 4; p++) {
                    int j = bj * 32 + cc + p;
                    if (j >= i) {
                        C[i * LL + j] = s[p];
                        C[j * LL + i] = s[p];
                        lmax = fmaxf(lmax, fabsf(s[p]));
                    }
                }
            }
        }
        if (lane == 0) atomicMax(&g_maxabs[n], __float_as_uint(lmax));
        return;
    }

    // ================= MLP ROLE (148 persistent CTAs) =================
    const uint32_t sb = smem_u32(smem);
    if (tid == 0) {
        MBAR_INIT(sb + 16, 128); MBAR_INIT(sb + 24, 128);
        MBAR_INIT(sb + 32, 256); MBAR_INIT(sb + 40, 256);
    }
    for (int i = tid; i < 16384; i += 384) {
        int k = i >> 7, nn = i & 127;
        ((__half*)(smem + WHI_OFF))[k * 136 + nn] = __float2half_rn(W1[i]);
    }
    if (tid < 128) {
        ((float*)(smem + B1S_OFF))[tid] = b1[tid];
        ((float*)(smem + W2S_OFF))[tid] = W2[tid];
    }
    __syncthreads();

    if (tid >= 256) {
        // ---- PRODUCERS (warps 8-11) ----
        const int ptid = tid - 256;
        int lc = 0;
        for (int chunk = blockIdx.x; chunk < NCHUNK; chunk += MLP_GRID, ++lc) {
            const int s = lc & 1;
            if (lc >= 2) MBAR_WAIT(sb + 32 + s * 8, ((lc >> 1) - 1) & 1);
            const float4* src = (const float4*)(f + (size_t)chunk * 16384);
            char* ahi = smem + A_OFF + s * ATILE;
#pragma unroll 4
            for (int q = 0; q < 32; q++) {
                int idx = q * 128 + ptid;
                float4 v = __ldg(src + idx);
                int row = idx >> 5, colq = (idx & 31) << 2;
                int off = row * PITCHB + colq * 2;
                *(uint2*)(ahi + off) = make_uint2(
                    pack_h16(__float2half_rn(v.x), __float2half_rn(v.y)),
                    pack_h16(__float2half_rn(v.z), __float2half_rn(v.w)));
            }
            MBAR_ARRIVE(sb + 16 + s * 8);
        }
    } else {
        // ---- CONSUMERS (warps 0-7) ----
        const int lane = tid & 31, wid = tid >> 5;
        const int warpM = wid >> 1, warpN = wid & 1;
        const int t = lane & 3, g = lane >> 2;
        const int lr = lane & 15, lh = lane >> 4;
        const float b2v = __ldg(b2);
        const float* sh_b1 = (const float*)(smem + B1S_OFF);
        const float* sh_w2 = (const float*)(smem + W2S_OFF);
        float* sp = (float*)(smem + SP_OFF);
        const uint32_t a_off = (uint32_t)((warpM * 32 + lr) * PITCHB + lh * 16);
        const uint32_t b_off = (uint32_t)(lr * PITCHB + (warpN * 64 + lh * 8) * 2);

        int lc = 0;
        for (int chunk = blockIdx.x; chunk < NCHUNK; chunk += MLP_GRID, ++lc) {
            const int s = lc & 1;
            MBAR_WAIT(sb + 16 + s * 8, (lc >> 1) & 1);
            const uint32_t sa_hi = sb + A_OFF + s * ATILE;

            float D[2][8][4];
#pragma unroll
            for (int i = 0; i < 2; i++)
#pragma unroll
                for (int j = 0; j < 8; j++)
#pragma unroll
                    for (int q = 0; q < 4; q++) D[i][j][q] = 0.0f;

#pragma unroll
            for (int ks = 0; ks < 8; ks++) {
                uint32_t ah0[4], ah1[4];
                LDSM_X4(ah0, sa_hi + a_off + ks * 32);
                LDSM_X4(ah1, sa_hi + a_off + 16 * PITCHB + ks * 32);
                uint32_t bh[8][2];
#pragma unroll
                for (int p = 0; p < 4; p++) {
                    uint32_t r[4];
                    LDSM_X4T(r, sb + WHI_OFF + b_off + ks * (16 * PITCHB) + p * 32);
                    bh[2*p][0] = r[0]; bh[2*p][1] = r[1];
                    bh[2*p+1][0] = r[2]; bh[2*p+1][1] = r[3];
                }
#pragma unroll
                for (int nf = 0; nf < 8; nf++) {
                    MMA_F16(D[0][nf], ah0, bh[nf]);
                    MMA_F16(D[1][nf], ah1, bh[nf]);
                }
            }
            MBAR_ARRIVE(sb + 32 + s * 8);

            float out_lo[2], out_hi[2];
#pragma unroll
            for (int mf = 0; mf < 2; mf++) {
                float plo = 0.0f, phi = 0.0f;
#pragma unroll
                for (int nf = 0; nf < 8; nf++) {
                    int col = warpN * 64 + nf * 8 + 2 * t;
                    float b1a = sh_b1[col], b1b = sh_b1[col + 1];
                    float w2a = sh_w2[col], w2b = sh_w2[col + 1];
                    plo += ftanh(D[mf][nf][0] + b1a) * w2a + ftanh(D[mf][nf][1] + b1b) * w2b;
                    phi += ftanh(D[mf][nf][2] + b1a) * w2a + ftanh(D[mf][nf][3] + b1b) * w2b;
                }
                plo += __shfl_xor_sync(0xffffffffu, plo, 1);
                plo += __shfl_xor_sync(0xffffffffu, plo, 2);
                phi += __shfl_xor_sync(0xffffffffu, phi, 1);
                phi += __shfl_xor_sync(0xffffffffu, phi, 2);
                out_lo[mf] = plo; out_hi[mf] = phi;
            }
            const int par = lc & 1;
            if (warpN == 0 && t == 0) {
#pragma unroll
                for (int mf = 0; mf < 2; mf++) {
                    int row = warpM * 32 + mf * 16 + g;
                    sp[par * 128 + row]     = out_lo[mf];
                    sp[par * 128 + row + 8] = out_hi[mf];
                }
            }
            asm volatile("bar.sync 1, 256;" ::: "memory");
            if (warpN == 1 && t == 0) {
                float* so = scores + (size_t)chunk * 128;
#pragma unroll
                for (int mf = 0; mf < 2; mf++) {
                    int row = warpM * 32 + mf * 16 + g;
                    so[row]     = out_lo[mf] + sp[par * 128 + row]     + b2v;
                    so[row + 8] = out_hi[mf] + sp[par * 128 + row + 8] + b2v;
                }
            }
        }
    }
}

// -------- kexp: K=exp(-LAM*Cn), KM=K*Cn -> split bf16, MMA-A-permuted --------
__global__ void kexp_kernel() {
    int idx = blockIdx.x * blockDim.x + threadIdx.x;
    int n = idx >> 16;
    int r = (idx >> 8) & 255, k = idx & 255;
    float mx = __uint_as_float(g_maxabs[n]);
    float cn = g_C[idx] / (mx + EPSF);
    float kv = __expf(-LAMF * cn);
    float km = kv * cn;
    int mt = r >> 4, rl = r & 15, kt = k >> 4, kl = k & 15;
    int T   = ((rl & 7) << 2) + ((kl & 7) >> 1);
    int reg = (rl >> 3) + ((kl >> 3) << 1);
    int pofs = (n << 16) + (((mt << 4) + kt) << 8) + (T << 3) + (reg << 1) + (kl & 1);
    __nv_bfloat16 kh = __float2bfloat16(kv);
    __nv_bfloat16 mh = __float2bfloat16(km);
    g_Kph [pofs] = kh;
    g_Kpl [pofs] = __float2bfloat16(kv - __bfloat162float(kh));
    g_KMph[pofs] = mh;
    g_KMpl[pofs] = __float2bfloat16(km - __bfloat162float(mh));
}

// ============ fused Sinkhorn (512 threads, 16 warps, one m16 tile/warp) ============
#define SK_XHI 0
#define SK_XLO 20480
#define SK_UN  40960
#define SK_CN  74752
#define SK_UF  108544
#define SK_RED 142336
#define SK_SMEM 142400

template<bool STORE_U>
__device__ __noinline__ void sink_phase(
    const uint4* __restrict__ Ah, const uint4* __restrict__ Al,
    uint32_t xhi, uint32_t xlo, uint32_t nmb, uint32_t ufb, int w, int lane)
{
    float D[4][4];
#pragma unroll
    for (int j = 0; j < 4; j++)
#pragma unroll
        for (int q = 0; q < 4; q++) D[j][q] = 0.0f;

    const int lr = lane & 15, lh = lane >> 4;
    const uint32_t bhb = xhi + lr * 80 + lh * 16;
    const uint32_t blb = xlo + lr * 80 + lh * 16;
#pragma unroll 4
    for (int kt = 0; kt < 16; kt++) {
        uint4 ah = Ah[(size_t)(w * 16 + kt) * 32 + lane];
        uint4 al = Al[(size_t)(w * 16 + kt) * 32 + lane];
        uint32_t bh[4][2], bl[4][2], r[4];
        LDSM_X4T(r, bhb + kt * 1280);      bh[0][0]=r[0]; bh[0][1]=r[1]; bh[1][0]=r[2]; bh[1][1]=r[3];
        LDSM_X4T(r, bhb + kt * 1280 + 32); bh[2][0]=r[0]; bh[2][1]=r[1]; bh[3][0]=r[2]; bh[3][1]=r[3];
        LDSM_X4T(r, blb + kt * 1280);      bl[0][0]=r[0]; bl[0][1]=r[1]; bl[1][0]=r[2]; bl[1][1]=r[3];
        LDSM_X4T(r, blb + kt * 1280 + 32); bl[2][0]=r[0]; bl[2][1]=r[1]; bl[3][0]=r[2]; bl[3][1]=r[3];
#pragma unroll
        for (int nt = 0; nt < 4; nt++) {
            MMA_BF16(D[nt], ((uint32_t*)&ah), bh[nt]);
            MMA_BF16(D[nt], ((uint32_t*)&al), bh[nt]);
            MMA_BF16(D[nt], ((uint32_t*)&ah), bl[nt]);
        }
    }
    __syncthreads();
    const int rq = lane >> 2, cq = (lane & 3) * 2;
    const int row = w * 16 + rq;
#pragma unroll
    for (int nt = 0; nt < 4; nt++) {
        int col = nt * 8 + cq;
        float n0 = lds32f(nmb + (row * 33 + col) * 4);
        float n1 = lds32f(nmb + (row * 33 + col + 1) * 4);
        float n2 = lds32f(nmb + ((row + 8) * 33 + col) * 4);
        float n3 = lds32f(nmb + ((row + 8) * 33 + col + 1) * 4);
        float o0 = __fdividef(n0, D[nt][0] + EPSF);
        float o1 = __fdividef(n1, D[nt][1] + EPSF);
        float o2 = __fdividef(n2, D[nt][2] + EPSF);
        float o3 = __fdividef(n3, D[nt][3] + EPSF);
        uint32_t h01, h23, l01, l23;
        CVT2BF(h01, o1, o0);
        CVT2BF(h23, o3, o2);
        float l0 = o0 - __uint_as_float(h01 << 16);
        float l1 = o1 - __uint_as_float(h01 & 0xffff0000u);
        float l2 = o2 - __uint_as_float(h23 << 16);
        float l3 = o3 - __uint_as_float(h23 & 0xffff0000u);
        CVT2BF(l01, l1, l0);
        CVT2BF(l23, l3, l2);
        sts32(xhi + row * 80 + col * 2, h01);
        sts32(xhi + (row + 8) * 80 + col * 2, h23);
        sts32(xlo + row * 80 + col * 2, l01);
        sts32(xlo + (row + 8) * 80 + col * 2, l23);
        if (STORE_U) {
            sts32f(ufb + (row * 33 + col) * 4, o0);
            sts32f(ufb + (row * 33 + col + 1) * 4, o1);
            sts32f(ufb + ((row + 8) * 33 + col) * 4, o2);
            sts32f(ufb + ((row + 8) * 33 + col + 1) * 4, o3);
        }
    }
    __syncthreads();
}

__global__ void __launch_bounds__(512, 1) sinkhorn_fused_kernel(
    const float* __restrict__ scores, const float* __restrict__ head,
    float* __restrict__ loss)
{
    extern __shared__ __align__(16) char smem[];
    const uint32_t sb = smem_u32(smem);
    const int tid = threadIdx.x, lane = tid & 31, w = tid >> 5;
    const int n = blockIdx.x >> 3, c0 = (blockIdx.x & 7) * 32;

    float* UN = (float*)(smem + SK_UN);
    float* CN = (float*)(smem + SK_CN);
#pragma unroll
    for (int q = 0; q < 2; q++) {
        int p = w * 2 + q;
        const float* row = scores + ((size_t)(n * 256 + c0 + p)) * 256;
        float4 v0 = *(const float4*)(row + lane * 4);
        float4 v1 = *(const float4*)(row + 128 + lane * 4);
        float m = fmaxf(fmaxf(fmaxf(v0.x, v0.y), fmaxf(v0.z, v0.w)),
                        fmaxf(fmaxf(v1.x, v1.y), fmaxf(v1.z, v1.w)));
#pragma unroll
        for (int o = 16; o > 0; o >>= 1) m = fmaxf(m, __shfl_xor_sync(0xffffffffu, m, o));
        float e[8];
        e[0] = __expf(v0.x - m); e[1] = __expf(v0.y - m);
        e[2] = __expf(v0.z - m); e[3] = __expf(v0.w - m);
        e[4] = __expf(v1.x - m); e[5] = __expf(v1.y - m);
        e[6] = __expf(v1.z - m); e[7] = __expf(v1.w - m);
        float sum = e[0]+e[1]+e[2]+e[3]+e[4]+e[5]+e[6]+e[7];
#pragma unroll
        for (int o = 16; o > 0; o >>= 1) sum += __shfl_xor_sync(0xffffffffu, sum, o);
        float inv = __fdividef(1.0f, sum);
#pragma unroll
        for (int k = 0; k < 4; k++) UN[(lane * 4 + k) * 33 + p]       = e[k] * inv;
#pragma unroll
        for (int k = 0; k < 4; k++) UN[(128 + lane * 4 + k) * 33 + p] = e[4 + k] * inv;

        const float* hrow = head + ((size_t)(n * 256 + c0 + p)) * 256;
        float4 h0 = *(const float4*)(hrow + lane * 4);
        float4 h1 = *(const float4*)(hrow + 128 + lane * 4);
        float he[8] = { h0.x + EPSF, h0.y + EPSF, h0.z + EPSF, h0.w + EPSF,
                        h1.x + EPSF, h1.y + EPSF, h1.z + EPSF, h1.w + EPSF };
        float hsum = he[0]+he[1]+he[2]+he[3]+he[4]+he[5]+he[6]+he[7];
#pragma unroll
        for (int o = 16; o > 0; o >>= 1) hsum += __shfl_xor_sync(0xffffffffu, hsum, o);
        float hinv = __fdividef(1.0f, hsum);
#pragma unroll
        for (int k = 0; k < 4; k++) CN[(lane * 4 + k) * 33 + p]       = he[k] * hinv;
#pragma unroll
        for (int k = 0; k < 4; k++) CN[(128 + lane * 4 + k) * 33 + p] = he[4 + k] * hinv;
    }
    const uint32_t HV = pack_bf16(__float2bfloat16(1.0f / 256.0f),
                                  __float2bfloat16(1.0f / 256.0f));
    for (int i = tid; i < 5120; i += 512) {
        ((uint32_t*)(smem + SK_XHI))[i] = HV;
        ((uint32_t*)(smem + SK_XLO))[i] = 0u;
    }
    __syncthreads();

    const uint4* Kh  = (const uint4*)g_Kph  + (size_t)n * 8192;
    const uint4* Kl  = (const uint4*)g_Kpl  + (size_t)n * 8192;
    const uint4* Mh  = (const uint4*)g_KMph + (size_t)n * 8192;
    const uint4* Ml  = (const uint4*)g_KMpl + (size_t)n * 8192;
    const uint32_t xhi = sb + SK_XHI, xlo = sb + SK_XLO;
    const uint32_t unb = sb + SK_UN, cnb = sb + SK_CN, ufb = sb + SK_UF;

#pragma unroll 1
    for (int it = 0; it < 19; it++) {
        sink_phase<false>(Kh, Kl, xhi, xlo, cnb, ufb, w, lane);
        sink_phase<false>(Kh, Kl, xhi, xlo, unb, ufb, w, lane);
    }
    sink_phase<false>(Kh, Kl, xhi, xlo, cnb, ufb, w, lane);
    sink_phase<true >(Kh, Kl, xhi, xlo, unb, ufb, w, lane);
    sink_phase<false>(Kh, Kl, xhi, xlo, cnb, ufb, w, lane);

    // loss partial: sum uF .* (KM @ v)
    float D[4][4];
#pragma unroll
    for (int j = 0; j < 4; j++)
#pragma unroll
        for (int q = 0; q < 4; q++) D[j][q] = 0.0f;
    {
        const int lr = lane & 15, lh = lane >> 4;
        const uint32_t bhb = xhi + lr * 80 + lh * 16;
        const uint32_t blb = xlo + lr * 80 + lh * 16;
#pragma unroll 4
        for (int kt = 0; kt < 16; kt++) {
            uint4 ah = Mh[(size_t)(w * 16 + kt) * 32 + lane];
            uint4 al = Ml[(size_t)(w * 16 + kt) * 32 + lane];
            uint32_t bh[4][2], bl[4][2], r[4];
            LDSM_X4T(r, bhb + kt * 1280);      bh[0][0]=r[0]; bh[0][1]=r[1]; bh[1][0]=r[2]; bh[1][1]=r[3];
            LDSM_X4T(r, bhb + kt * 1280 + 32); bh[2][0]=r[0]; bh[2][1]=r[1]; bh[3][0]=r[2]; bh[3][1]=r[3];
            LDSM_X4T(r, blb + kt * 1280);      bl[0][0]=r[0]; bl[0][1]=r[1]; bl[1][0]=r[2]; bl[1][1]=r[3];
            LDSM_X4T(r, blb + kt * 1280 + 32); bl[2][0]=r[0]; bl[2][1]=r[1]; bl[3][0]=r[2]; bl[3][1]=r[3];
#pragma unroll
            for (int nt = 0; nt < 4; nt++) {
                MMA_BF16(D[nt], ((uint32_t*)&ah), bh[nt]);
                MMA_BF16(D[nt], ((uint32_t*)&al), bh[nt]);
                MMA_BF16(D[nt], ((uint32_t*)&ah), bl[nt]);
            }
        }
    }
    float part = 0.0f;
    {
        const int rq = lane >> 2, cq = (lane & 3) * 2;
        const int row = w * 16 + rq;
#pragma unroll
        for (int nt = 0; nt < 4; nt++) {
            int col = nt * 8 + cq;
            part += lds32f(ufb + (row * 33 + col) * 4)           * D[nt][0];
            part += lds32f(ufb + (row * 33 + col + 1) * 4)       * D[nt][1];
            part += lds32f(ufb + ((row + 8) * 33 + col) * 4)     * D[nt][2];
            part += lds32f(ufb + ((row + 8) * 33 + col + 1) * 4) * D[nt][3];
        }
    }
#pragma unroll
    for (int o = 16; o > 0; o >>= 1) part += __shfl_xor_sync(0xffffffffu, part, o);
    float* RED = (float*)(smem + SK_RED);
    if (lane == 0) RED[w] = part;
    __syncthreads();
    if (tid == 0) {
        float t = 0.0f;
#pragma unroll
        for (int i = 0; i < 16; i++) t += RED[i];
        atomicAdd(loss, t);
    }
}

extern "C" void kernel_launch(void* const* d_in, const int* in_sizes, int n_in,
                              void* d_out, int out_size)
{
    const float* f    = (const float*)d_in[0];
    const float* head = (const float*)d_in[1];
    const float* W1   = (const float*)d_in[2];
    const float* b1   = (const float*)d_in[3];
    const float* W2   = (const float*)d_in[4];
    const float* b2   = (const float*)d_in[5];
    float* out    = (float*)d_out;
    float* scores = out;
    float* loss   = out + (out_size - 1);

    cudaFuncSetAttribute(merged_kernel, cudaFuncAttributeMaxDynamicSharedMemorySize, MLP_SMEM);
    cudaFuncSetAttribute(sinkhorn_fused_kernel, cudaFuncAttributeMaxDynamicSharedMemorySize, SK_SMEM);

    init_kernel<<<1, 256>>>(loss);
    merged_kernel<<<MLP_GRID + COST_GRID, 384, MLP_SMEM>>>(f, W1, b1, W2, b2, scores);
    kexp_kernel<<<NARC / 256, 256>>>();
    sinkhorn_fused_kernel<<<128, 512, SK_SMEM>>>(scores, head, loss);
}